// round 11
// baseline (speedup 1.0000x reference)
#include <cuda_runtime.h>
#include <math.h>

#define N_FFT   2048
#define HOP     512
#define NT      2880000
#define NFRAMES 5626            // 1 + NT/HOP
#define NPAIRS  2813            // NFRAMES/2
#define PAD     1024            // N_FFT/2
#define NCH     2

#define CHUNK     512
#define WARM      16384
#define NC        5625          // NT / CHUNK (exact)
#define NTILES    528           // (WARM + CHUNK) / 32
#define WARMTILES 512           // WARM / 32

#define TWO_PI_F 6.2831853071795864769f
#define LN10_F   2.3025850929940457f

// Scratch (device globals — no allocation allowed)
__device__ float g_sigA[NCH * NT];
__device__ float g_sigB[NCH * NT];
__device__ float g_frames[NCH * NFRAMES * N_FFT];   // reused as gs after OLA4
__device__ float g_win[N_FFT];

struct C2 { float x, y; };
__device__ __forceinline__ C2 cmulC(C2 a, C2 b) { return { a.x*b.x - a.y*b.y, a.x*b.y + a.y*b.x }; }
__device__ __forceinline__ C2 caddC(C2 a, C2 b) { return { a.x + b.x, a.y + b.y }; }
__device__ __forceinline__ C2 csubC(C2 a, C2 b) { return { a.x - b.x, a.y - b.y }; }

__device__ __forceinline__ int SWZ(int p) { return p + (p >> 5); }

// 4-byte async copy GMEM -> SMEM (LDGSTS), no register transit
__device__ __forceinline__ void cp_async4(void* sdst, const float* gsrc) {
    unsigned s = (unsigned)__cvta_generic_to_shared(sdst);
    asm volatile("cp.async.ca.shared.global [%0], [%1], 4;" :: "r"(s), "l"(gsrc) : "memory");
}

// fill hann window (accurate path, computed once per launch)
__global__ void win_init_kernel()
{
    int j = blockIdx.x * blockDim.x + threadIdx.x;
    if (j < N_FFT)
        g_win[j] = 0.5f - 0.5f * cosf((TWO_PI_F / (float)N_FFT) * (float)j);
}

template<int SGN>
__device__ __forceinline__ void dft8(C2 v[8]) {
    const float r = 0.70710678118654752f;
    const float S = (float)SGN;
    C2 a0 = caddC(v[0], v[4]), a1 = csubC(v[0], v[4]);
    C2 a2 = caddC(v[2], v[6]), a3 = csubC(v[2], v[6]);
    C2 E0 = caddC(a0, a2), E2 = csubC(a0, a2);
    C2 E1 = { a1.x - S * a3.y, a1.y + S * a3.x };
    C2 E3 = { a1.x + S * a3.y, a1.y - S * a3.x };
    C2 b0 = caddC(v[1], v[5]), b1 = csubC(v[1], v[5]);
    C2 b2 = caddC(v[3], v[7]), b3 = csubC(v[3], v[7]);
    C2 O0 = caddC(b0, b2), O2 = csubC(b0, b2);
    C2 O1 = { b1.x - S * b3.y, b1.y + S * b3.x };
    C2 O3 = { b1.x + S * b3.y, b1.y - S * b3.x };
    C2 T1 = { r * (O1.x - S * O1.y), r * (O1.y + S * O1.x) };
    C2 T2 = { -S * O2.y, S * O2.x };
    C2 T3 = { -r * (O3.x + S * O3.y), r * (S * O3.x - O3.y) };
    v[0] = caddC(E0, O0); v[4] = csubC(E0, O0);
    v[1] = caddC(E1, T1); v[5] = csubC(E1, T1);
    v[2] = caddC(E2, T2); v[6] = csubC(E2, T2);
    v[3] = caddC(E3, T3); v[7] = csubC(E3, T3);
}

// 16-point DFT: two dft8 halves + constant rotations
template<int SGN>
__device__ __forceinline__ void dft16(C2 v[16]) {
    const float S = (float)SGN;
    const float c1 = 0.92387953251128675613f;   // cos(pi/8)
    const float s1 = 0.38268343236508977173f;   // sin(pi/8)
    const float r  = 0.70710678118654752440f;
    C2 e[8], o[8];
#pragma unroll
    for (int i = 0; i < 8; ++i) { e[i] = v[2*i]; o[i] = v[2*i+1]; }
    dft8<SGN>(e);
    dft8<SGN>(o);
    o[1] = cmulC(o[1], C2{ c1, S*s1});
    o[2] = cmulC(o[2], C2{ r,  S*r });
    o[3] = cmulC(o[3], C2{ s1, S*c1});
    o[4] = C2{ -S*o[4].y, S*o[4].x };
    o[5] = cmulC(o[5], C2{-s1, S*c1});
    o[6] = cmulC(o[6], C2{-r,  S*r });
    o[7] = cmulC(o[7], C2{-c1, S*s1});
#pragma unroll
    for (int k = 0; k < 8; ++k) { v[k] = caddC(e[k], o[k]); v[k+8] = csubC(e[k], o[k]); }
}

// twiddle powers W[1..15] of w1 via a depth-4 product tree
__device__ __forceinline__ void twiddle_pows(C2 w1, C2 W[16]) {
    W[1] = w1;
    W[2] = cmulC(w1, w1);
    W[4] = cmulC(W[2], W[2]);
    W[8] = cmulC(W[4], W[4]);
    W[3] = cmulC(W[2], w1);
    W[5] = cmulC(W[4], w1);
    W[6] = cmulC(W[4], W[2]);
    W[7] = cmulC(W[4], W[3]);
    W[9]  = cmulC(W[8], w1);
    W[10] = cmulC(W[8], W[2]);
    W[11] = cmulC(W[8], W[3]);
    W[12] = cmulC(W[8], W[4]);
    W[13] = cmulC(W[8], W[5]);
    W[14] = cmulC(W[8], W[6]);
    W[15] = cmulC(W[8], W[7]);
}

// one radix-16 exchange stage
template<int SGN>
__device__ __forceinline__ void stage16(float2* sh, int M, int j, int base) {
    const int span = M >> 4;
    const int p0 = base + j;
    C2 v[16];
#pragma unroll
    for (int k = 0; k < 16; ++k) {
        float2 t = sh[SWZ(p0 + k * span)];
        v[k] = { t.x, t.y };
    }
    float sn, cs;
    __sincosf(((float)SGN * TWO_PI_F) * ((float)j / (float)M), &sn, &cs);
    C2 W[16];
    twiddle_pows(C2{ cs, sn }, W);
    if (SGN < 0) {
        dft16<-1>(v);
#pragma unroll
        for (int k = 1; k < 16; ++k) v[k] = cmulC(v[k], W[k]);
    } else {
#pragma unroll
        for (int k = 1; k < 16; ++k) v[k] = cmulC(v[k], W[k]);
        dft16<1>(v);
    }
#pragma unroll
    for (int k = 0; k < 16; ++k)
        sh[SWZ(p0 + k * span)] = make_float2(v[k].x, v[k].y);
}

// One block = one (channel, frame-pair). Two real frames packed into one complex FFT.
// 2048 = 16 x 16 x 8: two radix-16 exchange stages + fused radix-8 with real/even mask.
// storage p = d1*128 + d2*8 + i  <->  frequency k = d1 + 16*d2 + 256*i
__global__ void __launch_bounds__(128)
eq_pair_kernel(const float* __restrict__ x, float* __restrict__ frames,
               const float* __restrict__ gain_db_ptr, float fc)
{
    __shared__ float2 sh[N_FFT + (N_FFT >> 5)];

    const int tid = threadIdx.x;
    const int P = blockIdx.x;
    const int c = blockIdx.y;
    const int f0 = 2 * P;

    const float* xc = x + c * NT;

#pragma unroll
    for (int k = 0; k < 16; ++k) {
        int j = tid + 128 * k;
        float w = g_win[j];
        int s0 = f0 * HOP + j - PAD;
        if (s0 < 0) s0 = -s0;
        if (s0 >= NT) s0 = 2 * NT - 2 - s0;
        int s1 = (f0 + 1) * HOP + j - PAD;
        if (s1 < 0) s1 = -s1;
        if (s1 >= NT) s1 = 2 * NT - 2 - s1;
        sh[SWZ(j)] = make_float2(xc[s0] * w, xc[s1] * w);
    }
    __syncthreads();

    stage16<-1>(sh, 2048, tid, 0);
    __syncthreads();
    stage16<-1>(sh, 128, tid & 7, (tid >> 3) << 7);
    __syncthreads();

    // fused: forward radix-8 + mask + inverse radix-8 (2 groups/thread)
    {
        float gdb = gain_db_ptr[0];
        float gm1 = __expf(gdb * 0.05f * LN10_F) - 1.f;
        float inv_fc = 1.f / fc;
#pragma unroll
        for (int h = 0; h < 2; ++h) {
            int base = tid * 16 + h * 8;
            C2 u[8];
#pragma unroll
            for (int i = 0; i < 8; ++i) {
                float2 t = sh[SWZ(base + i)];
                u[i] = { t.x, t.y };
            }
            dft8<-1>(u);
            int d1 = (base >> 7) & 15, d2 = (base >> 3) & 15;
            int kbase = d1 + (d2 << 4);
#pragma unroll
            for (int i = 0; i < 8; ++i) {
                int kk = kbase + (i << 8);
                int ks = min(kk, N_FFT - kk);
                float fr = (float)ks * (24000.f / 1024.f);
                float rr = (fr - fc) * inv_fc;    // q = 1
                float fac = 1.f + gm1 * __expf(-rr * rr);
                u[i].x *= fac; u[i].y *= fac;
            }
            dft8<1>(u);
#pragma unroll
            for (int i = 0; i < 8; ++i)
                sh[SWZ(base + i)] = make_float2(u[i].x, u[i].y);
        }
    }
    __syncthreads();

    stage16<1>(sh, 128, tid & 7, (tid >> 3) << 7);
    __syncthreads();
    stage16<1>(sh, 2048, tid, 0);
    __syncthreads();

    float* fo0 = frames + (c * NFRAMES + f0) * N_FFT;
    float* fo1 = fo0 + N_FFT;
#pragma unroll
    for (int k = 0; k < 16; ++k) {
        int j = tid + 128 * k;
        float2 t = sh[SWZ(j)];
        float s = g_win[j] * (1.f / (float)N_FFT);
        fo0[j] = t.x * s;
        fo1[j] = t.y * s;
    }
}

// OLA. Interior (all 4 frames present): wsum == 1.5 exactly (Hann^2, 4x overlap).
__device__ __forceinline__ float ola_at(const float* __restrict__ frames, int c, int t)
{
    int tt = t + PAD;
    int fhi = tt >> 9;
    if (tt >= (N_FFT - HOP) && fhi <= NFRAMES - 1) {
        const float* base = frames + c * NFRAMES * N_FFT;
        int f = fhi - 3;
        int n = tt - f * HOP;   // in [1536, 2048)
        float s = base[f * N_FFT + n]
                + base[(f + 1) * N_FFT + (n - HOP)]
                + base[(f + 2) * N_FFT + (n - 2 * HOP)]
                + base[(f + 3) * N_FFT + (n - 3 * HOP)];
        return s * (2.f / 3.f);
    }
    int fmax = fhi;                                    if (fmax > NFRAMES - 1) fmax = NFRAMES - 1;
    int fmin = (tt - (N_FFT - 1) + (HOP - 1)) / HOP;   if (fmin < 0) fmin = 0;
    float sum = 0.f, ws = 0.f;
    for (int f = fmin; f <= fmax; ++f) {
        int n = tt - f * HOP;
        sum += frames[(c * NFRAMES + f) * N_FFT + n];
        float w = g_win[n];
        ws += w * w;
    }
    return sum / (ws > 1e-11f ? ws : 1.f);
}

__global__ void ola_kernel(const float* __restrict__ frames, float* __restrict__ out)
{
    int idx = blockIdx.x * blockDim.x + threadIdx.x;
    if (idx >= NCH * NT) return;
    int c = idx / NT;
    int t = idx - c * NT;
    out[idx] = ola_at(frames, c, t);
}

// final OLA fused with gain-reduction computation
__global__ void ola_gr_kernel(const float* __restrict__ frames, float* __restrict__ out,
                              float* __restrict__ gr,
                              const float* __restrict__ thr_p, const float* __restrict__ ratio_p)
{
    int idx = blockIdx.x * blockDim.x + threadIdx.x;
    if (idx >= NCH * NT) return;
    int c = idx / NT;
    int t = idx - c * NT;
    float v = ola_at(frames, c, t);
    out[idx] = v;
    float thr = thr_p[0];
    float ratio = ratio_p[0];
    float aa = fabsf(v) + 1e-8f;
    float adb = 20.f * __log10f(aa);
    gr[idx] = fmaxf(adb - thr, 0.f) * (1.f - 1.f / ratio);
}

// Warp-cooperative compressor scan with cp.async (LDGSTS) staging:
//   - next tile copied GMEM->SMEM by the async engine (no register transit, no
//     scoreboard stall in the warp's chain)
//   - wait_group 1 keeps exactly one tile in flight, overlapped with this tile's chain
//   - chain reads via a batched gv[32] LDS preload, then pure FFMA/FMNMX
// R10's nx[32]+gv[32] register staging (~90 regs) left ~270us of per-tile stall;
// this drops live registers to ~55 and moves the copy off the warp entirely.
// Recurrence (exact, branchless): state' = max(fma(1-a_att,s,a_att*g), fma(1-a_rel,s,a_rel*g))
__global__ void __launch_bounds__(128, 1)
scan_kernel(const float* __restrict__ gr, float* __restrict__ gs,
            const float* __restrict__ att_p, const float* __restrict__ rel_p)
{
    __shared__ float sbuf[4][2][32][33];

    const int w = threadIdx.x >> 5;
    const int lane = threadIdx.x & 31;
    const int warpGlobal = blockIdx.x * 4 + w;
    const int chunkBase = warpGlobal * 32;
    if (chunkBase >= NC) return;                 // warp-uniform
    const int c = blockIdx.y;
    const int myChunk = chunkBase + lane;

    const float a_att = 1.f - __expf(-1.f / (att_p[0] * 48000.f));
    const float a_rel = 1.f - __expf(-1.f / (rel_p[0] * 48000.f));
    const float m_att = 1.f - a_att, m_rel = 1.f - a_rel;

    const float* grc = gr + c * NT;
    float* gsc = gs + c * NT;

    const int base00 = chunkBase * CHUNK - WARM + lane;
    const bool needClamp = (warpGlobal == 0) || (chunkBase + 32 > NC);

    float state = 0.f;

#define STEP(gv) state = fmaxf(fmaf(m_att, state, a_att * (gv)), fmaf(m_rel, state, a_rel * (gv)))

// async-copy one tile (32 rows x 32 lanes) into buffer b; one commit group
#define ISSUE(d, b) do {                                                \
        int _b0 = base00 + (d) * 32;                                    \
        if (needClamp) {                                                \
            _Pragma("unroll")                                           \
            for (int r = 0; r < 32; ++r) {                              \
                int _a = _b0 + r * CHUNK;                               \
                _a = max(0, min(_a, NT - 1));                           \
                cp_async4(&sbuf[w][b][r][lane], grc + _a);              \
            }                                                           \
        } else {                                                        \
            _Pragma("unroll")                                           \
            for (int r = 0; r < 32; ++r)                                \
                cp_async4(&sbuf[w][b][r][lane], grc + _b0 + r * CHUNK); \
        }                                                               \
        asm volatile("cp.async.commit_group;" ::: "memory");            \
    } while (0)

    ISSUE(0, 0);

    for (int d = 0; d < NTILES; ++d) {
        const int b = d & 1;
        if (d + 1 < NTILES) {
            ISSUE(d + 1, (d + 1) & 1);
            asm volatile("cp.async.wait_group 1;" ::: "memory");   // tile d's group done
        } else {
            asm volatile("cp.async.wait_group 0;" ::: "memory");
        }
        __syncwarp();

        // batch-preload this tile's row (independent LDS, conflict-free stride-33)
        float gv[32];
#pragma unroll
        for (int j = 0; j < 32; ++j) gv[j] = sbuf[w][b][lane][j];

        const int tfirst = myChunk * CHUNK - WARM + d * 32;

        if (d < WARMTILES) {
            if (tfirst >= 1) {
#pragma unroll
                for (int j = 0; j < 32; ++j) STEP(gv[j]);
            } else {
#pragma unroll
                for (int j = 0; j < 32; ++j) {
                    if (tfirst + j >= 1) STEP(gv[j]);
                }
            }
        } else {
            // store tile: scan + write states into smem, then cooperative coalesced store
            if (tfirst >= 1) {
#pragma unroll
                for (int j = 0; j < 32; ++j) {
                    STEP(gv[j]);
                    sbuf[w][b][lane][j] = state;
                }
            } else {
#pragma unroll
                for (int j = 0; j < 32; ++j) {
                    if (tfirst + j >= 1) STEP(gv[j]);
                    sbuf[w][b][lane][j] = state;   // at t=0 state==0 -> gs[0]=0
                }
            }
            __syncwarp();
            int toff = (d - WARMTILES) * 32 + lane;
#pragma unroll 8
            for (int r = 0; r < 32; ++r) {
                int ch = chunkBase + r;
                if (ch < NC) gsc[ch * CHUNK + toff] = sbuf[w][b][r][lane];
            }
        }
        __syncwarp();
    }
#undef STEP
#undef ISSUE
}

// apply smoothed gain + makeup, then saturation
__global__ void final_kernel(const float* __restrict__ x, const float* __restrict__ gs,
                             float* __restrict__ out,
                             const float* __restrict__ makeup_p, const float* __restrict__ sat_p)
{
    int idx = blockIdx.x * blockDim.x + threadIdx.x;
    if (idx >= NCH * NT) return;
    float mk = makeup_p[0];
    float sat = sat_p[0];
    float xv = x[idx];
    float aa = fabsf(xv) + 1e-8f;
    float gl = __expf((mk - gs[idx]) * 0.05f * LN10_F);
    float sgn = (xv > 0.f) ? 1.f : ((xv < 0.f) ? -1.f : 0.f);
    float y = sgn * aa * gl;
    if (sat > 1.f) {
        float z = y * sat;
        float e = __expf(2.f * z);
        y = ((e - 1.f) / (e + 1.f)) / sat;
    }
    out[idx] = y;
}

extern "C" void kernel_launch(void* const* d_in, const int* in_sizes, int n_in,
                              void* d_out, int out_size)
{
    const float* audio      = (const float*)d_in[0];
    const float* eq_low     = (const float*)d_in[1];
    const float* eq_lowmid  = (const float*)d_in[2];
    const float* eq_highmid = (const float*)d_in[3];
    const float* eq_high    = (const float*)d_in[4];
    const float* thr        = (const float*)d_in[5];
    const float* ratio      = (const float*)d_in[6];
    const float* attack     = (const float*)d_in[7];
    const float* release    = (const float*)d_in[8];
    const float* makeup     = (const float*)d_in[9];
    const float* satur      = (const float*)d_in[10];
    float* out = (float*)d_out;

    float *sigA, *sigB, *frames;
    cudaGetSymbolAddress((void**)&sigA, g_sigA);
    cudaGetSymbolAddress((void**)&sigB, g_sigB);
    cudaGetSymbolAddress((void**)&frames, g_frames);
    float* gs = frames;   // frames buffer reused after final OLA

    dim3 gEq(NPAIRS, NCH);
    const int EW = 256;
    int ewBlocks = (NCH * NT + EW - 1) / EW;

    win_init_kernel<<<(N_FFT + 255) / 256, 256>>>();

    // EQ band chain (ping-pong)
    eq_pair_kernel<<<gEq, 128>>>(audio, frames, eq_low, 100.f);
    ola_kernel<<<ewBlocks, EW>>>(frames, sigA);
    eq_pair_kernel<<<gEq, 128>>>(sigA, frames, eq_lowmid, 500.f);
    ola_kernel<<<ewBlocks, EW>>>(frames, sigB);
    eq_pair_kernel<<<gEq, 128>>>(sigB, frames, eq_highmid, 3000.f);
    ola_kernel<<<ewBlocks, EW>>>(frames, sigA);
    eq_pair_kernel<<<gEq, 128>>>(sigA, frames, eq_high, 10000.f);
    // band 4 OLA fused with gain-reduction: audio -> sigB, gr -> sigA
    ola_gr_kernel<<<ewBlocks, EW>>>(frames, sigB, sigA, thr, ratio);

    // cp.async-pipelined warp-cooperative compressor envelope (gs into frames buffer)
    int nWarpsPerCh = (NC + 31) / 32;                  // 176
    dim3 gScan((nWarpsPerCh + 3) / 4, NCH);            // 44 x 2 blocks, 4 warps each
    scan_kernel<<<gScan, 128>>>(sigA, gs, attack, release);

    // gain + saturation
    final_kernel<<<ewBlocks, EW>>>(sigB, gs, out, makeup, satur);
}

// round 12
// speedup vs baseline: 1.2202x; 1.2202x over previous
#include <cuda_runtime.h>
#include <math.h>

#define N_FFT   2048
#define HOP     512
#define NT      2880000
#define NFRAMES 5626            // 1 + NT/HOP
#define NPAIRS  2813            // NFRAMES/2
#define PAD     1024            // N_FFT/2
#define NCH     2

#define CHUNK     512
#define WARM      14336
#define NC        5625          // NT / CHUNK (exact)
#define NTILES    464           // (WARM + CHUNK) / 32
#define WARMTILES 448           // WARM / 32

#define TWO_PI_F 6.2831853071795864769f
#define LN10_F   2.3025850929940457f

// Scratch (device globals — no allocation allowed)
__device__ float g_sigA[NCH * NT];
__device__ float g_sigB[NCH * NT];
__device__ float g_frames[NCH * NFRAMES * N_FFT];   // reused as gs after OLA4
__device__ float g_win[N_FFT];

struct C2 { float x, y; };
__device__ __forceinline__ C2 cmulC(C2 a, C2 b) { return { a.x*b.x - a.y*b.y, a.x*b.y + a.y*b.x }; }
__device__ __forceinline__ C2 caddC(C2 a, C2 b) { return { a.x + b.x, a.y + b.y }; }
__device__ __forceinline__ C2 csubC(C2 a, C2 b) { return { a.x - b.x, a.y - b.y }; }

__device__ __forceinline__ int SWZ(int p) { return p + (p >> 5); }

// fill hann window (accurate path, computed once per launch)
__global__ void win_init_kernel()
{
    int j = blockIdx.x * blockDim.x + threadIdx.x;
    if (j < N_FFT)
        g_win[j] = 0.5f - 0.5f * cosf((TWO_PI_F / (float)N_FFT) * (float)j);
}

template<int SGN>
__device__ __forceinline__ void dft8(C2 v[8]) {
    const float r = 0.70710678118654752f;
    const float S = (float)SGN;
    C2 a0 = caddC(v[0], v[4]), a1 = csubC(v[0], v[4]);
    C2 a2 = caddC(v[2], v[6]), a3 = csubC(v[2], v[6]);
    C2 E0 = caddC(a0, a2), E2 = csubC(a0, a2);
    C2 E1 = { a1.x - S * a3.y, a1.y + S * a3.x };
    C2 E3 = { a1.x + S * a3.y, a1.y - S * a3.x };
    C2 b0 = caddC(v[1], v[5]), b1 = csubC(v[1], v[5]);
    C2 b2 = caddC(v[3], v[7]), b3 = csubC(v[3], v[7]);
    C2 O0 = caddC(b0, b2), O2 = csubC(b0, b2);
    C2 O1 = { b1.x - S * b3.y, b1.y + S * b3.x };
    C2 O3 = { b1.x + S * b3.y, b1.y - S * b3.x };
    C2 T1 = { r * (O1.x - S * O1.y), r * (O1.y + S * O1.x) };
    C2 T2 = { -S * O2.y, S * O2.x };
    C2 T3 = { -r * (O3.x + S * O3.y), r * (S * O3.x - O3.y) };
    v[0] = caddC(E0, O0); v[4] = csubC(E0, O0);
    v[1] = caddC(E1, T1); v[5] = csubC(E1, T1);
    v[2] = caddC(E2, T2); v[6] = csubC(E2, T2);
    v[3] = caddC(E3, T3); v[7] = csubC(E3, T3);
}

// 16-point DFT: two dft8 halves + constant rotations
template<int SGN>
__device__ __forceinline__ void dft16(C2 v[16]) {
    const float S = (float)SGN;
    const float c1 = 0.92387953251128675613f;   // cos(pi/8)
    const float s1 = 0.38268343236508977173f;   // sin(pi/8)
    const float r  = 0.70710678118654752440f;
    C2 e[8], o[8];
#pragma unroll
    for (int i = 0; i < 8; ++i) { e[i] = v[2*i]; o[i] = v[2*i+1]; }
    dft8<SGN>(e);
    dft8<SGN>(o);
    o[1] = cmulC(o[1], C2{ c1, S*s1});
    o[2] = cmulC(o[2], C2{ r,  S*r });
    o[3] = cmulC(o[3], C2{ s1, S*c1});
    o[4] = C2{ -S*o[4].y, S*o[4].x };
    o[5] = cmulC(o[5], C2{-s1, S*c1});
    o[6] = cmulC(o[6], C2{-r,  S*r });
    o[7] = cmulC(o[7], C2{-c1, S*s1});
#pragma unroll
    for (int k = 0; k < 8; ++k) { v[k] = caddC(e[k], o[k]); v[k+8] = csubC(e[k], o[k]); }
}

// twiddle powers W[1..15] of w1 via a depth-4 product tree
__device__ __forceinline__ void twiddle_pows(C2 w1, C2 W[16]) {
    W[1] = w1;
    W[2] = cmulC(w1, w1);
    W[4] = cmulC(W[2], W[2]);
    W[8] = cmulC(W[4], W[4]);
    W[3] = cmulC(W[2], w1);
    W[5] = cmulC(W[4], w1);
    W[6] = cmulC(W[4], W[2]);
    W[7] = cmulC(W[4], W[3]);
    W[9]  = cmulC(W[8], w1);
    W[10] = cmulC(W[8], W[2]);
    W[11] = cmulC(W[8], W[3]);
    W[12] = cmulC(W[8], W[4]);
    W[13] = cmulC(W[8], W[5]);
    W[14] = cmulC(W[8], W[6]);
    W[15] = cmulC(W[8], W[7]);
}

// one radix-16 exchange stage
template<int SGN>
__device__ __forceinline__ void stage16(float2* sh, int M, int j, int base) {
    const int span = M >> 4;
    const int p0 = base + j;
    C2 v[16];
#pragma unroll
    for (int k = 0; k < 16; ++k) {
        float2 t = sh[SWZ(p0 + k * span)];
        v[k] = { t.x, t.y };
    }
    float sn, cs;
    __sincosf(((float)SGN * TWO_PI_F) * ((float)j / (float)M), &sn, &cs);
    C2 W[16];
    twiddle_pows(C2{ cs, sn }, W);
    if (SGN < 0) {
        dft16<-1>(v);
#pragma unroll
        for (int k = 1; k < 16; ++k) v[k] = cmulC(v[k], W[k]);
    } else {
#pragma unroll
        for (int k = 1; k < 16; ++k) v[k] = cmulC(v[k], W[k]);
        dft16<1>(v);
    }
#pragma unroll
    for (int k = 0; k < 16; ++k)
        sh[SWZ(p0 + k * span)] = make_float2(v[k].x, v[k].y);
}

// One block = one (channel, frame-pair). Two real frames packed into one complex FFT.
// 2048 = 16 x 16 x 8: two radix-16 exchange stages + fused radix-8 with real/even mask.
// storage p = d1*128 + d2*8 + i  <->  frequency k = d1 + 16*d2 + 256*i
__global__ void __launch_bounds__(128)
eq_pair_kernel(const float* __restrict__ x, float* __restrict__ frames,
               const float* __restrict__ gain_db_ptr, float fc)
{
    __shared__ float2 sh[N_FFT + (N_FFT >> 5)];

    const int tid = threadIdx.x;
    const int P = blockIdx.x;
    const int c = blockIdx.y;
    const int f0 = 2 * P;

    const float* xc = x + c * NT;

#pragma unroll
    for (int k = 0; k < 16; ++k) {
        int j = tid + 128 * k;
        float w = g_win[j];
        int s0 = f0 * HOP + j - PAD;
        if (s0 < 0) s0 = -s0;
        if (s0 >= NT) s0 = 2 * NT - 2 - s0;
        int s1 = (f0 + 1) * HOP + j - PAD;
        if (s1 < 0) s1 = -s1;
        if (s1 >= NT) s1 = 2 * NT - 2 - s1;
        sh[SWZ(j)] = make_float2(xc[s0] * w, xc[s1] * w);
    }
    __syncthreads();

    stage16<-1>(sh, 2048, tid, 0);
    __syncthreads();
    stage16<-1>(sh, 128, tid & 7, (tid >> 3) << 7);
    __syncthreads();

    // fused: forward radix-8 + mask + inverse radix-8 (2 groups/thread)
    {
        float gdb = gain_db_ptr[0];
        float gm1 = __expf(gdb * 0.05f * LN10_F) - 1.f;
        float inv_fc = 1.f / fc;
#pragma unroll
        for (int h = 0; h < 2; ++h) {
            int base = tid * 16 + h * 8;
            C2 u[8];
#pragma unroll
            for (int i = 0; i < 8; ++i) {
                float2 t = sh[SWZ(base + i)];
                u[i] = { t.x, t.y };
            }
            dft8<-1>(u);
            int d1 = (base >> 7) & 15, d2 = (base >> 3) & 15;
            int kbase = d1 + (d2 << 4);
#pragma unroll
            for (int i = 0; i < 8; ++i) {
                int kk = kbase + (i << 8);
                int ks = min(kk, N_FFT - kk);
                float fr = (float)ks * (24000.f / 1024.f);
                float rr = (fr - fc) * inv_fc;    // q = 1
                float fac = 1.f + gm1 * __expf(-rr * rr);
                u[i].x *= fac; u[i].y *= fac;
            }
            dft8<1>(u);
#pragma unroll
            for (int i = 0; i < 8; ++i)
                sh[SWZ(base + i)] = make_float2(u[i].x, u[i].y);
        }
    }
    __syncthreads();

    stage16<1>(sh, 128, tid & 7, (tid >> 3) << 7);
    __syncthreads();
    stage16<1>(sh, 2048, tid, 0);
    __syncthreads();

    float* fo0 = frames + (c * NFRAMES + f0) * N_FFT;
    float* fo1 = fo0 + N_FFT;
#pragma unroll
    for (int k = 0; k < 16; ++k) {
        int j = tid + 128 * k;
        float2 t = sh[SWZ(j)];
        float s = g_win[j] * (1.f / (float)N_FFT);
        fo0[j] = t.x * s;
        fo1[j] = t.y * s;
    }
}

// OLA. Interior (all 4 frames present): wsum == 1.5 exactly (Hann^2, 4x overlap).
__device__ __forceinline__ float ola_at(const float* __restrict__ frames, int c, int t)
{
    int tt = t + PAD;
    int fhi = tt >> 9;
    if (tt >= (N_FFT - HOP) && fhi <= NFRAMES - 1) {
        const float* base = frames + c * NFRAMES * N_FFT;
        int f = fhi - 3;
        int n = tt - f * HOP;   // in [1536, 2048)
        float s = base[f * N_FFT + n]
                + base[(f + 1) * N_FFT + (n - HOP)]
                + base[(f + 2) * N_FFT + (n - 2 * HOP)]
                + base[(f + 3) * N_FFT + (n - 3 * HOP)];
        return s * (2.f / 3.f);
    }
    int fmax = fhi;                                    if (fmax > NFRAMES - 1) fmax = NFRAMES - 1;
    int fmin = (tt - (N_FFT - 1) + (HOP - 1)) / HOP;   if (fmin < 0) fmin = 0;
    float sum = 0.f, ws = 0.f;
    for (int f = fmin; f <= fmax; ++f) {
        int n = tt - f * HOP;
        sum += frames[(c * NFRAMES + f) * N_FFT + n];
        float w = g_win[n];
        ws += w * w;
    }
    return sum / (ws > 1e-11f ? ws : 1.f);
}

__global__ void ola_kernel(const float* __restrict__ frames, float* __restrict__ out)
{
    int idx = blockIdx.x * blockDim.x + threadIdx.x;
    if (idx >= NCH * NT) return;
    int c = idx / NT;
    int t = idx - c * NT;
    out[idx] = ola_at(frames, c, t);
}

// final OLA fused with gain-reduction computation
__global__ void ola_gr_kernel(const float* __restrict__ frames, float* __restrict__ out,
                              float* __restrict__ gr,
                              const float* __restrict__ thr_p, const float* __restrict__ ratio_p)
{
    int idx = blockIdx.x * blockDim.x + threadIdx.x;
    if (idx >= NCH * NT) return;
    int c = idx / NT;
    int t = idx - c * NT;
    float v = ola_at(frames, c, t);
    out[idx] = v;
    float thr = thr_p[0];
    float ratio = ratio_p[0];
    float aa = fabsf(v) + 1e-8f;
    float adb = 20.f * __log10f(aa);
    gr[idx] = fmaxf(adb - thr, 0.f) * (1.f - 1.f / ratio);
}

// Warp-cooperative compressor scan v3 (dual-chain, float4-staged).
// Each warp owns 64 consecutive chunks: lane l runs TWO interleaved recurrence chains
// (chunks base+l and base+32+l) so the second chain's FMAs fill the first chain's
// 8-cyc dependency stalls (a warp is in-order; a single chain leaves the SMSP idle).
// Tile staging: 16 x LDG.128 per lane (issue 64 cyc for 64 rows) -> registers ->
// STS after the chain (LDG latency hidden under the chain) -> conflict-free smem.
// Vector clamp to [0, NT-4] is exact: tiles are 4-aligned so no float4 straddles t=0;
// clamped elements are precisely the guarded (t<1) or never-stored (chunk>=NC) ones.
// Recurrence (exact, branchless): state' = max(fma(1-a_att,s,a_att*g), fma(1-a_rel,s,a_rel*g))
__global__ void __launch_bounds__(64, 2)
scan_kernel(const float* __restrict__ gr, float* __restrict__ gs,
            const float* __restrict__ att_p, const float* __restrict__ rel_p)
{
    __shared__ float sbuf[2][2][64][33];   // [warp][dblbuf][row=chunk][col=step]

    const int w = threadIdx.x >> 5;
    const int lane = threadIdx.x & 31;
    const int warpGlobal = blockIdx.x * 2 + w;
    const int chunkBase = warpGlobal * 64;     // max 87*64=5568 < NC
    const int c = blockIdx.y;

    const float a_att = 1.f - __expf(-1.f / (att_p[0] * 48000.f));
    const float a_rel = 1.f - __expf(-1.f / (rel_p[0] * 48000.f));
    const float m_att = 1.f - a_att, m_rel = 1.f - a_rel;

    const float* grc = gr + c * NT;
    float* gsc = gs + c * NT;

    const int row0 = lane >> 3;          // 0..3
    const int quad = (lane & 7) << 2;    // 0,4,..,28
    const bool clampW = (warpGlobal == 0) || (chunkBase + 64 > NC);
    const bool guardW = (warpGlobal == 0);

    float state0 = 0.f, state1 = 0.f;
    float4 nx[16];

#define STEP0(gv) state0 = fmaxf(fmaf(m_att, state0, a_att * (gv)), fmaf(m_rel, state0, a_rel * (gv)))
#define STEP1(gv) state1 = fmaxf(fmaf(m_att, state1, a_att * (gv)), fmaf(m_rel, state1, a_rel * (gv)))

// 16 x LDG.128 per lane: load i covers row i*4+row0, cols quad..quad+3 of tile dd
#define LOADT(dd) do {                                                        \
        int _tb = chunkBase * CHUNK - WARM + (dd) * 32 + quad;                \
        if (clampW) {                                                         \
            _Pragma("unroll")                                                 \
            for (int i = 0; i < 16; ++i) {                                    \
                int _a = _tb + (i * 4 + row0) * CHUNK;                        \
                _a = max(0, min(_a, NT - 4));                                 \
                nx[i] = *(const float4*)(grc + _a);                           \
            }                                                                 \
        } else {                                                              \
            _Pragma("unroll")                                                 \
            for (int i = 0; i < 16; ++i)                                      \
                nx[i] = *(const float4*)(grc + _tb + (i * 4 + row0) * CHUNK); \
        }                                                                     \
    } while (0)

#define STORET(bb) do {                                                       \
        _Pragma("unroll")                                                     \
        for (int i = 0; i < 16; ++i) {                                        \
            int _r = i * 4 + row0;                                            \
            sbuf[w][bb][_r][quad + 0] = nx[i].x;                              \
            sbuf[w][bb][_r][quad + 1] = nx[i].y;                              \
            sbuf[w][bb][_r][quad + 2] = nx[i].z;                              \
            sbuf[w][bb][_r][quad + 3] = nx[i].w;                              \
        }                                                                     \
    } while (0)

    LOADT(0);
    STORET(0);
    __syncwarp();

    // ---- warm phase (no output) ----
    for (int d = 0; d < WARMTILES; ++d) {
        const int b = d & 1;
        LOADT(d + 1);
        const int tf0 = (chunkBase + lane) * CHUNK - WARM + d * 32;
#pragma unroll
        for (int grp = 0; grp < 4; ++grp) {
            float p0[8], p1[8];
#pragma unroll
            for (int j = 0; j < 8; ++j) {
                p0[j] = sbuf[w][b][lane][grp * 8 + j];
                p1[j] = sbuf[w][b][32 + lane][grp * 8 + j];
            }
            if (guardW) {
#pragma unroll
                for (int j = 0; j < 8; ++j) {
                    if (tf0 + grp * 8 + j >= 1) STEP0(p0[j]);
                    STEP1(p1[j]);   // second-half chunks always have full history
                }
            } else {
#pragma unroll
                for (int j = 0; j < 8; ++j) { STEP0(p0[j]); STEP1(p1[j]); }
            }
        }
        STORET((d + 1) & 1);
        __syncwarp();
    }

    // ---- store phase ----
    for (int d = WARMTILES; d < NTILES; ++d) {
        const int b = d & 1;
        if (d + 1 < NTILES) LOADT(d + 1);
        const int tf0 = (chunkBase + lane) * CHUNK - WARM + d * 32;
#pragma unroll
        for (int grp = 0; grp < 4; ++grp) {
            float p0[8], p1[8];
#pragma unroll
            for (int j = 0; j < 8; ++j) {
                p0[j] = sbuf[w][b][lane][grp * 8 + j];
                p1[j] = sbuf[w][b][32 + lane][grp * 8 + j];
            }
            if (guardW) {
#pragma unroll
                for (int j = 0; j < 8; ++j) {
                    if (tf0 + grp * 8 + j >= 1) STEP0(p0[j]);
                    STEP1(p1[j]);
                    sbuf[w][b][lane][grp * 8 + j] = state0;        // t=0 -> state0==0 -> gs[0]=0
                    sbuf[w][b][32 + lane][grp * 8 + j] = state1;
                }
            } else {
#pragma unroll
                for (int j = 0; j < 8; ++j) {
                    STEP0(p0[j]); STEP1(p1[j]);
                    sbuf[w][b][lane][grp * 8 + j] = state0;
                    sbuf[w][b][32 + lane][grp * 8 + j] = state1;
                }
            }
        }
        __syncwarp();
        // cooperative coalesced store of 64 rows
        int toff = (d - WARMTILES) * 32 + lane;
#pragma unroll 8
        for (int r = 0; r < 64; ++r) {
            int ch = chunkBase + r;
            if (ch < NC) gsc[ch * CHUNK + toff] = sbuf[w][b][r][lane];
        }
        if (d + 1 < NTILES) STORET((d + 1) & 1);
        __syncwarp();
    }
#undef STEP0
#undef STEP1
#undef LOADT
#undef STORET
}

// apply smoothed gain + makeup, then saturation
__global__ void final_kernel(const float* __restrict__ x, const float* __restrict__ gs,
                             float* __restrict__ out,
                             const float* __restrict__ makeup_p, const float* __restrict__ sat_p)
{
    int idx = blockIdx.x * blockDim.x + threadIdx.x;
    if (idx >= NCH * NT) return;
    float mk = makeup_p[0];
    float sat = sat_p[0];
    float xv = x[idx];
    float aa = fabsf(xv) + 1e-8f;
    float gl = __expf((mk - gs[idx]) * 0.05f * LN10_F);
    float sgn = (xv > 0.f) ? 1.f : ((xv < 0.f) ? -1.f : 0.f);
    float y = sgn * aa * gl;
    if (sat > 1.f) {
        float z = y * sat;
        float e = __expf(2.f * z);
        y = ((e - 1.f) / (e + 1.f)) / sat;
    }
    out[idx] = y;
}

extern "C" void kernel_launch(void* const* d_in, const int* in_sizes, int n_in,
                              void* d_out, int out_size)
{
    const float* audio      = (const float*)d_in[0];
    const float* eq_low     = (const float*)d_in[1];
    const float* eq_lowmid  = (const float*)d_in[2];
    const float* eq_highmid = (const float*)d_in[3];
    const float* eq_high    = (const float*)d_in[4];
    const float* thr        = (const float*)d_in[5];
    const float* ratio      = (const float*)d_in[6];
    const float* attack     = (const float*)d_in[7];
    const float* release    = (const float*)d_in[8];
    const float* makeup     = (const float*)d_in[9];
    const float* satur      = (const float*)d_in[10];
    float* out = (float*)d_out;

    float *sigA, *sigB, *frames;
    cudaGetSymbolAddress((void**)&sigA, g_sigA);
    cudaGetSymbolAddress((void**)&sigB, g_sigB);
    cudaGetSymbolAddress((void**)&frames, g_frames);
    float* gs = frames;   // frames buffer reused after final OLA

    dim3 gEq(NPAIRS, NCH);
    const int EW = 256;
    int ewBlocks = (NCH * NT + EW - 1) / EW;

    win_init_kernel<<<(N_FFT + 255) / 256, 256>>>();

    // EQ band chain (ping-pong)
    eq_pair_kernel<<<gEq, 128>>>(audio, frames, eq_low, 100.f);
    ola_kernel<<<ewBlocks, EW>>>(frames, sigA);
    eq_pair_kernel<<<gEq, 128>>>(sigA, frames, eq_lowmid, 500.f);
    ola_kernel<<<ewBlocks, EW>>>(frames, sigB);
    eq_pair_kernel<<<gEq, 128>>>(sigB, frames, eq_highmid, 3000.f);
    ola_kernel<<<ewBlocks, EW>>>(frames, sigA);
    eq_pair_kernel<<<gEq, 128>>>(sigA, frames, eq_high, 10000.f);
    // band 4 OLA fused with gain-reduction: audio -> sigB, gr -> sigA
    ola_gr_kernel<<<ewBlocks, EW>>>(frames, sigB, sigA, thr, ratio);

    // dual-chain warp-cooperative compressor envelope (gs into frames buffer)
    // 88 warps per channel (64 chunks each), 2 warps per 64-thread block
    dim3 gScan(44, NCH);
    scan_kernel<<<gScan, 64>>>(sigA, gs, attack, release);

    // gain + saturation
    final_kernel<<<ewBlocks, EW>>>(sigB, gs, out, makeup, satur);
}

// round 13
// speedup vs baseline: 1.2733x; 1.0435x over previous
#include <cuda_runtime.h>
#include <math.h>

#define N_FFT   2048
#define HOP     512
#define NT      2880000
#define NFRAMES 5626            // 1 + NT/HOP
#define NPAIRS  2813            // NFRAMES/2
#define PAD     1024            // N_FFT/2
#define NCH     2

#define CHUNK     512
#define WARM      14336
#define NC        5625          // NT / CHUNK (exact)
#define NTILES    464           // (WARM + CHUNK) / 32
#define WARMTILES 448           // WARM / 32

#define TWO_PI_F 6.2831853071795864769f
#define LN10_F   2.3025850929940457f

// Scratch (device globals — no allocation allowed)
__device__ float g_sigA[NCH * NT];
__device__ float g_sigB[NCH * NT];
__device__ float g_frames[NCH * NFRAMES * N_FFT];   // reused as gs after OLA4
__device__ float g_win[N_FFT];

struct C2 { float x, y; };
__device__ __forceinline__ C2 cmulC(C2 a, C2 b) { return { a.x*b.x - a.y*b.y, a.x*b.y + a.y*b.x }; }
__device__ __forceinline__ C2 caddC(C2 a, C2 b) { return { a.x + b.x, a.y + b.y }; }
__device__ __forceinline__ C2 csubC(C2 a, C2 b) { return { a.x - b.x, a.y - b.y }; }

__device__ __forceinline__ int SWZ(int p) { return p + (p >> 5); }

// fill hann window (accurate path, computed once per launch)
__global__ void win_init_kernel()
{
    int j = blockIdx.x * blockDim.x + threadIdx.x;
    if (j < N_FFT)
        g_win[j] = 0.5f - 0.5f * cosf((TWO_PI_F / (float)N_FFT) * (float)j);
}

template<int SGN>
__device__ __forceinline__ void dft8(C2 v[8]) {
    const float r = 0.70710678118654752f;
    const float S = (float)SGN;
    C2 a0 = caddC(v[0], v[4]), a1 = csubC(v[0], v[4]);
    C2 a2 = caddC(v[2], v[6]), a3 = csubC(v[2], v[6]);
    C2 E0 = caddC(a0, a2), E2 = csubC(a0, a2);
    C2 E1 = { a1.x - S * a3.y, a1.y + S * a3.x };
    C2 E3 = { a1.x + S * a3.y, a1.y - S * a3.x };
    C2 b0 = caddC(v[1], v[5]), b1 = csubC(v[1], v[5]);
    C2 b2 = caddC(v[3], v[7]), b3 = csubC(v[3], v[7]);
    C2 O0 = caddC(b0, b2), O2 = csubC(b0, b2);
    C2 O1 = { b1.x - S * b3.y, b1.y + S * b3.x };
    C2 O3 = { b1.x + S * b3.y, b1.y - S * b3.x };
    C2 T1 = { r * (O1.x - S * O1.y), r * (O1.y + S * O1.x) };
    C2 T2 = { -S * O2.y, S * O2.x };
    C2 T3 = { -r * (O3.x + S * O3.y), r * (S * O3.x - O3.y) };
    v[0] = caddC(E0, O0); v[4] = csubC(E0, O0);
    v[1] = caddC(E1, T1); v[5] = csubC(E1, T1);
    v[2] = caddC(E2, T2); v[6] = csubC(E2, T2);
    v[3] = caddC(E3, T3); v[7] = csubC(E3, T3);
}

// 16-point DFT: two dft8 halves + constant rotations
template<int SGN>
__device__ __forceinline__ void dft16(C2 v[16]) {
    const float S = (float)SGN;
    const float c1 = 0.92387953251128675613f;   // cos(pi/8)
    const float s1 = 0.38268343236508977173f;   // sin(pi/8)
    const float r  = 0.70710678118654752440f;
    C2 e[8], o[8];
#pragma unroll
    for (int i = 0; i < 8; ++i) { e[i] = v[2*i]; o[i] = v[2*i+1]; }
    dft8<SGN>(e);
    dft8<SGN>(o);
    o[1] = cmulC(o[1], C2{ c1, S*s1});
    o[2] = cmulC(o[2], C2{ r,  S*r });
    o[3] = cmulC(o[3], C2{ s1, S*c1});
    o[4] = C2{ -S*o[4].y, S*o[4].x };
    o[5] = cmulC(o[5], C2{-s1, S*c1});
    o[6] = cmulC(o[6], C2{-r,  S*r });
    o[7] = cmulC(o[7], C2{-c1, S*s1});
#pragma unroll
    for (int k = 0; k < 8; ++k) { v[k] = caddC(e[k], o[k]); v[k+8] = csubC(e[k], o[k]); }
}

// twiddle powers W[1..15] of w1 via a depth-4 product tree
__device__ __forceinline__ void twiddle_pows(C2 w1, C2 W[16]) {
    W[1] = w1;
    W[2] = cmulC(w1, w1);
    W[4] = cmulC(W[2], W[2]);
    W[8] = cmulC(W[4], W[4]);
    W[3] = cmulC(W[2], w1);
    W[5] = cmulC(W[4], w1);
    W[6] = cmulC(W[4], W[2]);
    W[7] = cmulC(W[4], W[3]);
    W[9]  = cmulC(W[8], w1);
    W[10] = cmulC(W[8], W[2]);
    W[11] = cmulC(W[8], W[3]);
    W[12] = cmulC(W[8], W[4]);
    W[13] = cmulC(W[8], W[5]);
    W[14] = cmulC(W[8], W[6]);
    W[15] = cmulC(W[8], W[7]);
}

// one radix-16 exchange stage (smem -> smem)
template<int SGN>
__device__ __forceinline__ void stage16(float2* sh, int M, int j, int base) {
    const int span = M >> 4;
    const int p0 = base + j;
    C2 v[16];
#pragma unroll
    for (int k = 0; k < 16; ++k) {
        float2 t = sh[SWZ(p0 + k * span)];
        v[k] = { t.x, t.y };
    }
    float sn, cs;
    __sincosf(((float)SGN * TWO_PI_F) * ((float)j / (float)M), &sn, &cs);
    C2 W[16];
    twiddle_pows(C2{ cs, sn }, W);
    if (SGN < 0) {
        dft16<-1>(v);
#pragma unroll
        for (int k = 1; k < 16; ++k) v[k] = cmulC(v[k], W[k]);
    } else {
#pragma unroll
        for (int k = 1; k < 16; ++k) v[k] = cmulC(v[k], W[k]);
        dft16<1>(v);
    }
#pragma unroll
    for (int k = 0; k < 16; ++k)
        sh[SWZ(p0 + k * span)] = make_float2(v[k].x, v[k].y);
}

// One block = one (channel, frame-pair). Two real frames packed into one complex FFT.
// 2048 = 16 x 16 x 8. The FIRST radix-16 stage (M=2048, span=128) reads positions
// tid + 128k — exactly the windowed-load indices — so it consumes gmem directly.
// Symmetrically the LAST inverse stage writes windowed output straight to gmem.
// This removes 2 of 7 smem phases (eq was 82% L1-throughput bound).
// storage p = d1*128 + d2*8 + i  <->  frequency k = d1 + 16*d2 + 256*i
__global__ void __launch_bounds__(128)
eq_pair_kernel(const float* __restrict__ x, float* __restrict__ frames,
               const float* __restrict__ gain_db_ptr, float fc)
{
    __shared__ float2 sh[N_FFT + (N_FFT >> 5)];

    const int tid = threadIdx.x;
    const int P = blockIdx.x;
    const int c = blockIdx.y;
    const int f0 = 2 * P;

    const float* xc = x + c * NT;

    // ---- fused: windowed reflect-pad load + first forward radix-16 stage
    {
        C2 v[16];
#pragma unroll
        for (int k = 0; k < 16; ++k) {
            int j = tid + 128 * k;
            float w = g_win[j];
            int s0 = f0 * HOP + j - PAD;
            if (s0 < 0) s0 = -s0;
            if (s0 >= NT) s0 = 2 * NT - 2 - s0;
            int s1 = (f0 + 1) * HOP + j - PAD;
            if (s1 < 0) s1 = -s1;
            if (s1 >= NT) s1 = 2 * NT - 2 - s1;
            v[k] = { xc[s0] * w, xc[s1] * w };
        }
        float sn, cs;
        __sincosf(-(TWO_PI_F) * ((float)tid / (float)N_FFT), &sn, &cs);
        C2 W[16];
        twiddle_pows(C2{ cs, sn }, W);
        dft16<-1>(v);
#pragma unroll
        for (int k = 1; k < 16; ++k) v[k] = cmulC(v[k], W[k]);
#pragma unroll
        for (int k = 0; k < 16; ++k)
            sh[SWZ(tid + k * 128)] = make_float2(v[k].x, v[k].y);
    }
    __syncthreads();

    stage16<-1>(sh, 128, tid & 7, (tid >> 3) << 7);
    __syncthreads();

    // fused: forward radix-8 + mask + inverse radix-8 (2 groups/thread)
    {
        float gdb = gain_db_ptr[0];
        float gm1 = __expf(gdb * 0.05f * LN10_F) - 1.f;
        float inv_fc = 1.f / fc;
#pragma unroll
        for (int h = 0; h < 2; ++h) {
            int base = tid * 16 + h * 8;
            C2 u[8];
#pragma unroll
            for (int i = 0; i < 8; ++i) {
                float2 t = sh[SWZ(base + i)];
                u[i] = { t.x, t.y };
            }
            dft8<-1>(u);
            int d1 = (base >> 7) & 15, d2 = (base >> 3) & 15;
            int kbase = d1 + (d2 << 4);
#pragma unroll
            for (int i = 0; i < 8; ++i) {
                int kk = kbase + (i << 8);
                int ks = min(kk, N_FFT - kk);
                float fr = (float)ks * (24000.f / 1024.f);
                float rr = (fr - fc) * inv_fc;    // q = 1
                float fac = 1.f + gm1 * __expf(-rr * rr);
                u[i].x *= fac; u[i].y *= fac;
            }
            dft8<1>(u);
#pragma unroll
            for (int i = 0; i < 8; ++i)
                sh[SWZ(base + i)] = make_float2(u[i].x, u[i].y);
        }
    }
    __syncthreads();

    stage16<1>(sh, 128, tid & 7, (tid >> 3) << 7);
    __syncthreads();

    // ---- fused: last inverse radix-16 stage + windowed store to gmem
    {
        C2 v[16];
#pragma unroll
        for (int k = 0; k < 16; ++k) {
            float2 t = sh[SWZ(tid + k * 128)];
            v[k] = { t.x, t.y };
        }
        float sn, cs;
        __sincosf((TWO_PI_F) * ((float)tid / (float)N_FFT), &sn, &cs);
        C2 W[16];
        twiddle_pows(C2{ cs, sn }, W);
#pragma unroll
        for (int k = 1; k < 16; ++k) v[k] = cmulC(v[k], W[k]);
        dft16<1>(v);
        float* fo0 = frames + (c * NFRAMES + f0) * N_FFT;
        float* fo1 = fo0 + N_FFT;
#pragma unroll
        for (int k = 0; k < 16; ++k) {
            int j = tid + 128 * k;
            float s = g_win[j] * (1.f / (float)N_FFT);
            fo0[j] = v[k].x * s;
            fo1[j] = v[k].y * s;
        }
    }
}

// OLA. Interior (all 4 frames present): wsum == 1.5 exactly (Hann^2, 4x overlap).
__device__ __forceinline__ float ola_at(const float* __restrict__ frames, int c, int t)
{
    int tt = t + PAD;
    int fhi = tt >> 9;
    if (tt >= (N_FFT - HOP) && fhi <= NFRAMES - 1) {
        const float* base = frames + c * NFRAMES * N_FFT;
        int f = fhi - 3;
        int n = tt - f * HOP;   // in [1536, 2048)
        float s = base[f * N_FFT + n]
                + base[(f + 1) * N_FFT + (n - HOP)]
                + base[(f + 2) * N_FFT + (n - 2 * HOP)]
                + base[(f + 3) * N_FFT + (n - 3 * HOP)];
        return s * (2.f / 3.f);
    }
    int fmax = fhi;                                    if (fmax > NFRAMES - 1) fmax = NFRAMES - 1;
    int fmin = (tt - (N_FFT - 1) + (HOP - 1)) / HOP;   if (fmin < 0) fmin = 0;
    float sum = 0.f, ws = 0.f;
    for (int f = fmin; f <= fmax; ++f) {
        int n = tt - f * HOP;
        sum += frames[(c * NFRAMES + f) * N_FFT + n];
        float w = g_win[n];
        ws += w * w;
    }
    return sum / (ws > 1e-11f ? ws : 1.f);
}

__global__ void ola_kernel(const float* __restrict__ frames, float* __restrict__ out)
{
    int idx = blockIdx.x * blockDim.x + threadIdx.x;
    if (idx >= NCH * NT) return;
    int c = idx / NT;
    int t = idx - c * NT;
    out[idx] = ola_at(frames, c, t);
}

// final OLA fused with gain-reduction computation
__global__ void ola_gr_kernel(const float* __restrict__ frames, float* __restrict__ out,
                              float* __restrict__ gr,
                              const float* __restrict__ thr_p, const float* __restrict__ ratio_p)
{
    int idx = blockIdx.x * blockDim.x + threadIdx.x;
    if (idx >= NCH * NT) return;
    int c = idx / NT;
    int t = idx - c * NT;
    float v = ola_at(frames, c, t);
    out[idx] = v;
    float thr = thr_p[0];
    float ratio = ratio_p[0];
    float aa = fabsf(v) + 1e-8f;
    float adb = 20.f * __log10f(aa);
    gr[idx] = fmaxf(adb - thr, 0.f) * (1.f - 1.f / ratio);
}

// Warp-cooperative compressor scan v4 (dual-chain, float4, 2-tile prefetch distance).
// gr may be DRAM-resident (ola_gr streams 138MB > 126MB L2), so the LDG->STS consume
// distance must cover ~600 cyc: two register sets (nxA/nxB) give a full 2-compute
// distance:  iter d:  LOADT(d+2 -> set[d&1]);  compute(d);  STORET(set[1-(d&1)] = tile d+1).
// Recurrence (exact, branchless): state' = max(fma(1-a_att,s,a_att*g), fma(1-a_rel,s,a_rel*g))
__global__ void __launch_bounds__(64, 2)
scan_kernel(const float* __restrict__ gr, float* __restrict__ gs,
            const float* __restrict__ att_p, const float* __restrict__ rel_p)
{
    __shared__ float sbuf[2][2][64][33];   // [warp][dblbuf][row=chunk][col=step]

    const int w = threadIdx.x >> 5;
    const int lane = threadIdx.x & 31;
    const int warpGlobal = blockIdx.x * 2 + w;
    const int chunkBase = warpGlobal * 64;     // max 87*64=5568 < NC
    const int c = blockIdx.y;

    const float a_att = 1.f - __expf(-1.f / (att_p[0] * 48000.f));
    const float a_rel = 1.f - __expf(-1.f / (rel_p[0] * 48000.f));
    const float m_att = 1.f - a_att, m_rel = 1.f - a_rel;

    const float* grc = gr + c * NT;
    float* gsc = gs + c * NT;

    const int row0 = lane >> 3;          // 0..3
    const int quad = (lane & 7) << 2;    // 0,4,..,28
    const bool clampW = (warpGlobal == 0) || (chunkBase + 64 > NC);
    const bool guardW = (warpGlobal == 0);

    float state0 = 0.f, state1 = 0.f;
    float4 nxA[16], nxB[16];

#define STEP0(gv) state0 = fmaxf(fmaf(m_att, state0, a_att * (gv)), fmaf(m_rel, state0, a_rel * (gv)))
#define STEP1(gv) state1 = fmaxf(fmaf(m_att, state1, a_att * (gv)), fmaf(m_rel, state1, a_rel * (gv)))

// 16 x LDG.128: load i covers row i*4+row0, cols quad..quad+3 of tile dd -> nx
#define LOADT(dd, nx) do {                                                    \
        int _tb = chunkBase * CHUNK - WARM + (dd) * 32 + quad;                \
        if (clampW) {                                                         \
            _Pragma("unroll")                                                 \
            for (int i = 0; i < 16; ++i) {                                    \
                int _a = _tb + (i * 4 + row0) * CHUNK;                        \
                _a = max(0, min(_a, NT - 4));                                 \
                nx[i] = *(const float4*)(grc + _a);                           \
            }                                                                 \
        } else {                                                              \
            _Pragma("unroll")                                                 \
            for (int i = 0; i < 16; ++i)                                      \
                nx[i] = *(const float4*)(grc + _tb + (i * 4 + row0) * CHUNK); \
        }                                                                     \
    } while (0)

#define STORET(bb, nx) do {                                                   \
        _Pragma("unroll")                                                     \
        for (int i = 0; i < 16; ++i) {                                        \
            int _r = i * 4 + row0;                                            \
            sbuf[w][bb][_r][quad + 0] = nx[i].x;                              \
            sbuf[w][bb][_r][quad + 1] = nx[i].y;                              \
            sbuf[w][bb][_r][quad + 2] = nx[i].z;                              \
            sbuf[w][bb][_r][quad + 3] = nx[i].w;                              \
        }                                                                     \
    } while (0)

#define COMPUTE_WARM(b, d) do {                                               \
        const int tf0 = (chunkBase + lane) * CHUNK - WARM + (d) * 32;         \
        _Pragma("unroll")                                                     \
        for (int grp = 0; grp < 4; ++grp) {                                   \
            float p0[8], p1[8];                                               \
            _Pragma("unroll")                                                 \
            for (int j = 0; j < 8; ++j) {                                     \
                p0[j] = sbuf[w][b][lane][grp * 8 + j];                        \
                p1[j] = sbuf[w][b][32 + lane][grp * 8 + j];                   \
            }                                                                 \
            if (guardW) {                                                     \
                _Pragma("unroll")                                             \
                for (int j = 0; j < 8; ++j) {                                 \
                    if (tf0 + grp * 8 + j >= 1) STEP0(p0[j]);                 \
                    STEP1(p1[j]);                                             \
                }                                                             \
            } else {                                                          \
                _Pragma("unroll")                                             \
                for (int j = 0; j < 8; ++j) { STEP0(p0[j]); STEP1(p1[j]); }   \
            }                                                                 \
        }                                                                     \
    } while (0)

    // prologue: tile0 staged, tile1 in flight (nxB), tile2 loaded at iter 0
    LOADT(0, nxA);
    STORET(0, nxA);
    LOADT(1, nxB);
    __syncwarp();

    // ---- warm phase ----
    for (int d = 0; d < WARMTILES; ++d) {
        const int b = d & 1;
        if ((d & 1) == 0) {
            if (d + 2 < NTILES) LOADT(d + 2, nxA);
            COMPUTE_WARM(b, d);
            STORET((d + 1) & 1, nxB);
        } else {
            if (d + 2 < NTILES) LOADT(d + 2, nxB);
            COMPUTE_WARM(b, d);
            STORET((d + 1) & 1, nxA);
        }
        __syncwarp();
    }

    // ---- store phase ----   (WARMTILES is even -> parity pattern continues)
    for (int d = WARMTILES; d < NTILES; ++d) {
        const int b = d & 1;
        if ((d & 1) == 0) { if (d + 2 < NTILES) LOADT(d + 2, nxA); }
        else              { if (d + 2 < NTILES) LOADT(d + 2, nxB); }

        const int tf0 = (chunkBase + lane) * CHUNK - WARM + d * 32;
#pragma unroll
        for (int grp = 0; grp < 4; ++grp) {
            float p0[8], p1[8];
#pragma unroll
            for (int j = 0; j < 8; ++j) {
                p0[j] = sbuf[w][b][lane][grp * 8 + j];
                p1[j] = sbuf[w][b][32 + lane][grp * 8 + j];
            }
            if (guardW) {
#pragma unroll
                for (int j = 0; j < 8; ++j) {
                    if (tf0 + grp * 8 + j >= 1) STEP0(p0[j]);
                    STEP1(p1[j]);
                    sbuf[w][b][lane][grp * 8 + j] = state0;        // t=0 -> state0==0 -> gs[0]=0
                    sbuf[w][b][32 + lane][grp * 8 + j] = state1;
                }
            } else {
#pragma unroll
                for (int j = 0; j < 8; ++j) {
                    STEP0(p0[j]); STEP1(p1[j]);
                    sbuf[w][b][lane][grp * 8 + j] = state0;
                    sbuf[w][b][32 + lane][grp * 8 + j] = state1;
                }
            }
        }
        __syncwarp();
        // cooperative coalesced store of 64 rows
        int toff = (d - WARMTILES) * 32 + lane;
#pragma unroll 8
        for (int r = 0; r < 64; ++r) {
            int ch = chunkBase + r;
            if (ch < NC) gsc[ch * CHUNK + toff] = sbuf[w][b][r][lane];
        }
        if (d + 1 < NTILES) {
            if ((d & 1) == 0) STORET((d + 1) & 1, nxB);
            else              STORET((d + 1) & 1, nxA);
        }
        __syncwarp();
    }
#undef STEP0
#undef STEP1
#undef LOADT
#undef STORET
#undef COMPUTE_WARM
}

// apply smoothed gain + makeup, then saturation
__global__ void final_kernel(const float* __restrict__ x, const float* __restrict__ gs,
                             float* __restrict__ out,
                             const float* __restrict__ makeup_p, const float* __restrict__ sat_p)
{
    int idx = blockIdx.x * blockDim.x + threadIdx.x;
    if (idx >= NCH * NT) return;
    float mk = makeup_p[0];
    float sat = sat_p[0];
    float xv = x[idx];
    float aa = fabsf(xv) + 1e-8f;
    float gl = __expf((mk - gs[idx]) * 0.05f * LN10_F);
    float sgn = (xv > 0.f) ? 1.f : ((xv < 0.f) ? -1.f : 0.f);
    float y = sgn * aa * gl;
    if (sat > 1.f) {
        float z = y * sat;
        float e = __expf(2.f * z);
        y = ((e - 1.f) / (e + 1.f)) / sat;
    }
    out[idx] = y;
}

extern "C" void kernel_launch(void* const* d_in, const int* in_sizes, int n_in,
                              void* d_out, int out_size)
{
    const float* audio      = (const float*)d_in[0];
    const float* eq_low     = (const float*)d_in[1];
    const float* eq_lowmid  = (const float*)d_in[2];
    const float* eq_highmid = (const float*)d_in[3];
    const float* eq_high    = (const float*)d_in[4];
    const float* thr        = (const float*)d_in[5];
    const float* ratio      = (const float*)d_in[6];
    const float* attack     = (const float*)d_in[7];
    const float* release    = (const float*)d_in[8];
    const float* makeup     = (const float*)d_in[9];
    const float* satur      = (const float*)d_in[10];
    float* out = (float*)d_out;

    float *sigA, *sigB, *frames;
    cudaGetSymbolAddress((void**)&sigA, g_sigA);
    cudaGetSymbolAddress((void**)&sigB, g_sigB);
    cudaGetSymbolAddress((void**)&frames, g_frames);
    float* gs = frames;   // frames buffer reused after final OLA

    dim3 gEq(NPAIRS, NCH);
    const int EW = 256;
    int ewBlocks = (NCH * NT + EW - 1) / EW;

    win_init_kernel<<<(N_FFT + 255) / 256, 256>>>();

    // EQ band chain (ping-pong)
    eq_pair_kernel<<<gEq, 128>>>(audio, frames, eq_low, 100.f);
    ola_kernel<<<ewBlocks, EW>>>(frames, sigA);
    eq_pair_kernel<<<gEq, 128>>>(sigA, frames, eq_lowmid, 500.f);
    ola_kernel<<<ewBlocks, EW>>>(frames, sigB);
    eq_pair_kernel<<<gEq, 128>>>(sigB, frames, eq_highmid, 3000.f);
    ola_kernel<<<ewBlocks, EW>>>(frames, sigA);
    eq_pair_kernel<<<gEq, 128>>>(sigA, frames, eq_high, 10000.f);
    // band 4 OLA fused with gain-reduction: audio -> sigB, gr -> sigA
    ola_gr_kernel<<<ewBlocks, EW>>>(frames, sigB, sigA, thr, ratio);

    // dual-chain warp-cooperative compressor envelope (gs into frames buffer)
    dim3 gScan(44, NCH);
    scan_kernel<<<gScan, 64>>>(sigA, gs, attack, release);

    // gain + saturation
    final_kernel<<<ewBlocks, EW>>>(sigB, gs, out, makeup, satur);
}

// round 14
// speedup vs baseline: 1.3227x; 1.0388x over previous
#include <cuda_runtime.h>
#include <math.h>

#define N_FFT   2048
#define HOP     512
#define NT      2880000
#define NFRAMES 5626            // 1 + NT/HOP
#define NPAIRS  2813            // NFRAMES/2
#define PAD     1024            // N_FFT/2
#define NCH     2

#define CHUNK     256
#define WARM      13312
#define NC        11250         // NT / CHUNK (exact)
#define NTILES    424           // (WARM + CHUNK) / 32
#define WARMTILES 416           // WARM / 32

#define TWO_PI_F 6.2831853071795864769f
#define LN10_F   2.3025850929940457f

// Scratch (device globals — no allocation allowed)
__device__ float g_sigA[NCH * NT];
__device__ float g_sigB[NCH * NT];
__device__ float g_frames[NCH * NFRAMES * N_FFT];   // reused as gs after OLA4
__device__ float g_win[N_FFT];

struct C2 { float x, y; };
__device__ __forceinline__ C2 cmulC(C2 a, C2 b) { return { a.x*b.x - a.y*b.y, a.x*b.y + a.y*b.x }; }
__device__ __forceinline__ C2 caddC(C2 a, C2 b) { return { a.x + b.x, a.y + b.y }; }
__device__ __forceinline__ C2 csubC(C2 a, C2 b) { return { a.x - b.x, a.y - b.y }; }

__device__ __forceinline__ int SWZ(int p) { return p + (p >> 5); }

// fill hann window (accurate path, computed once per launch)
__global__ void win_init_kernel()
{
    int j = blockIdx.x * blockDim.x + threadIdx.x;
    if (j < N_FFT)
        g_win[j] = 0.5f - 0.5f * cosf((TWO_PI_F / (float)N_FFT) * (float)j);
}

template<int SGN>
__device__ __forceinline__ void dft8(C2 v[8]) {
    const float r = 0.70710678118654752f;
    const float S = (float)SGN;
    C2 a0 = caddC(v[0], v[4]), a1 = csubC(v[0], v[4]);
    C2 a2 = caddC(v[2], v[6]), a3 = csubC(v[2], v[6]);
    C2 E0 = caddC(a0, a2), E2 = csubC(a0, a2);
    C2 E1 = { a1.x - S * a3.y, a1.y + S * a3.x };
    C2 E3 = { a1.x + S * a3.y, a1.y - S * a3.x };
    C2 b0 = caddC(v[1], v[5]), b1 = csubC(v[1], v[5]);
    C2 b2 = caddC(v[3], v[7]), b3 = csubC(v[3], v[7]);
    C2 O0 = caddC(b0, b2), O2 = csubC(b0, b2);
    C2 O1 = { b1.x - S * b3.y, b1.y + S * b3.x };
    C2 O3 = { b1.x + S * b3.y, b1.y - S * b3.x };
    C2 T1 = { r * (O1.x - S * O1.y), r * (O1.y + S * O1.x) };
    C2 T2 = { -S * O2.y, S * O2.x };
    C2 T3 = { -r * (O3.x + S * O3.y), r * (S * O3.x - O3.y) };
    v[0] = caddC(E0, O0); v[4] = csubC(E0, O0);
    v[1] = caddC(E1, T1); v[5] = csubC(E1, T1);
    v[2] = caddC(E2, T2); v[6] = csubC(E2, T2);
    v[3] = caddC(E3, T3); v[7] = csubC(E3, T3);
}

// 16-point DFT: two dft8 halves + constant rotations
template<int SGN>
__device__ __forceinline__ void dft16(C2 v[16]) {
    const float S = (float)SGN;
    const float c1 = 0.92387953251128675613f;   // cos(pi/8)
    const float s1 = 0.38268343236508977173f;   // sin(pi/8)
    const float r  = 0.70710678118654752440f;
    C2 e[8], o[8];
#pragma unroll
    for (int i = 0; i < 8; ++i) { e[i] = v[2*i]; o[i] = v[2*i+1]; }
    dft8<SGN>(e);
    dft8<SGN>(o);
    o[1] = cmulC(o[1], C2{ c1, S*s1});
    o[2] = cmulC(o[2], C2{ r,  S*r });
    o[3] = cmulC(o[3], C2{ s1, S*c1});
    o[4] = C2{ -S*o[4].y, S*o[4].x };
    o[5] = cmulC(o[5], C2{-s1, S*c1});
    o[6] = cmulC(o[6], C2{-r,  S*r });
    o[7] = cmulC(o[7], C2{-c1, S*s1});
#pragma unroll
    for (int k = 0; k < 8; ++k) { v[k] = caddC(e[k], o[k]); v[k+8] = csubC(e[k], o[k]); }
}

// twiddle powers W[1..15] of w1 via a depth-4 product tree
__device__ __forceinline__ void twiddle_pows(C2 w1, C2 W[16]) {
    W[1] = w1;
    W[2] = cmulC(w1, w1);
    W[4] = cmulC(W[2], W[2]);
    W[8] = cmulC(W[4], W[4]);
    W[3] = cmulC(W[2], w1);
    W[5] = cmulC(W[4], w1);
    W[6] = cmulC(W[4], W[2]);
    W[7] = cmulC(W[4], W[3]);
    W[9]  = cmulC(W[8], w1);
    W[10] = cmulC(W[8], W[2]);
    W[11] = cmulC(W[8], W[3]);
    W[12] = cmulC(W[8], W[4]);
    W[13] = cmulC(W[8], W[5]);
    W[14] = cmulC(W[8], W[6]);
    W[15] = cmulC(W[8], W[7]);
}

// one radix-16 exchange stage (smem -> smem)
template<int SGN>
__device__ __forceinline__ void stage16(float2* sh, int M, int j, int base) {
    const int span = M >> 4;
    const int p0 = base + j;
    C2 v[16];
#pragma unroll
    for (int k = 0; k < 16; ++k) {
        float2 t = sh[SWZ(p0 + k * span)];
        v[k] = { t.x, t.y };
    }
    float sn, cs;
    __sincosf(((float)SGN * TWO_PI_F) * ((float)j / (float)M), &sn, &cs);
    C2 W[16];
    twiddle_pows(C2{ cs, sn }, W);
    if (SGN < 0) {
        dft16<-1>(v);
#pragma unroll
        for (int k = 1; k < 16; ++k) v[k] = cmulC(v[k], W[k]);
    } else {
#pragma unroll
        for (int k = 1; k < 16; ++k) v[k] = cmulC(v[k], W[k]);
        dft16<1>(v);
    }
#pragma unroll
    for (int k = 0; k < 16; ++k)
        sh[SWZ(p0 + k * span)] = make_float2(v[k].x, v[k].y);
}

// One block = one (channel, frame-pair). Two real frames packed into one complex FFT.
// 2048 = 16 x 16 x 8; first/last radix-16 stages fused with gmem load/store.
// storage p = d1*128 + d2*8 + i  <->  frequency k = d1 + 16*d2 + 256*i
__global__ void __launch_bounds__(128)
eq_pair_kernel(const float* __restrict__ x, float* __restrict__ frames,
               const float* __restrict__ gain_db_ptr, float fc)
{
    __shared__ float2 sh[N_FFT + (N_FFT >> 5)];

    const int tid = threadIdx.x;
    const int P = blockIdx.x;
    const int c = blockIdx.y;
    const int f0 = 2 * P;

    const float* xc = x + c * NT;

    // ---- fused: windowed reflect-pad load + first forward radix-16 stage
    {
        C2 v[16];
#pragma unroll
        for (int k = 0; k < 16; ++k) {
            int j = tid + 128 * k;
            float w = g_win[j];
            int s0 = f0 * HOP + j - PAD;
            if (s0 < 0) s0 = -s0;
            if (s0 >= NT) s0 = 2 * NT - 2 - s0;
            int s1 = (f0 + 1) * HOP + j - PAD;
            if (s1 < 0) s1 = -s1;
            if (s1 >= NT) s1 = 2 * NT - 2 - s1;
            v[k] = { xc[s0] * w, xc[s1] * w };
        }
        float sn, cs;
        __sincosf(-(TWO_PI_F) * ((float)tid / (float)N_FFT), &sn, &cs);
        C2 W[16];
        twiddle_pows(C2{ cs, sn }, W);
        dft16<-1>(v);
#pragma unroll
        for (int k = 1; k < 16; ++k) v[k] = cmulC(v[k], W[k]);
#pragma unroll
        for (int k = 0; k < 16; ++k)
            sh[SWZ(tid + k * 128)] = make_float2(v[k].x, v[k].y);
    }
    __syncthreads();

    stage16<-1>(sh, 128, tid & 7, (tid >> 3) << 7);
    __syncthreads();

    // fused: forward radix-8 + mask + inverse radix-8 (2 groups/thread)
    {
        float gdb = gain_db_ptr[0];
        float gm1 = __expf(gdb * 0.05f * LN10_F) - 1.f;
        float inv_fc = 1.f / fc;
#pragma unroll
        for (int h = 0; h < 2; ++h) {
            int base = tid * 16 + h * 8;
            C2 u[8];
#pragma unroll
            for (int i = 0; i < 8; ++i) {
                float2 t = sh[SWZ(base + i)];
                u[i] = { t.x, t.y };
            }
            dft8<-1>(u);
            int d1 = (base >> 7) & 15, d2 = (base >> 3) & 15;
            int kbase = d1 + (d2 << 4);
#pragma unroll
            for (int i = 0; i < 8; ++i) {
                int kk = kbase + (i << 8);
                int ks = min(kk, N_FFT - kk);
                float fr = (float)ks * (24000.f / 1024.f);
                float rr = (fr - fc) * inv_fc;    // q = 1
                float fac = 1.f + gm1 * __expf(-rr * rr);
                u[i].x *= fac; u[i].y *= fac;
            }
            dft8<1>(u);
#pragma unroll
            for (int i = 0; i < 8; ++i)
                sh[SWZ(base + i)] = make_float2(u[i].x, u[i].y);
        }
    }
    __syncthreads();

    stage16<1>(sh, 128, tid & 7, (tid >> 3) << 7);
    __syncthreads();

    // ---- fused: last inverse radix-16 stage + windowed store to gmem
    {
        C2 v[16];
#pragma unroll
        for (int k = 0; k < 16; ++k) {
            float2 t = sh[SWZ(tid + k * 128)];
            v[k] = { t.x, t.y };
        }
        float sn, cs;
        __sincosf((TWO_PI_F) * ((float)tid / (float)N_FFT), &sn, &cs);
        C2 W[16];
        twiddle_pows(C2{ cs, sn }, W);
#pragma unroll
        for (int k = 1; k < 16; ++k) v[k] = cmulC(v[k], W[k]);
        dft16<1>(v);
        float* fo0 = frames + (c * NFRAMES + f0) * N_FFT;
        float* fo1 = fo0 + N_FFT;
#pragma unroll
        for (int k = 0; k < 16; ++k) {
            int j = tid + 128 * k;
            float s = g_win[j] * (1.f / (float)N_FFT);
            fo0[j] = v[k].x * s;
            fo1[j] = v[k].y * s;
        }
    }
}

// OLA. Interior (all 4 frames present): wsum == 1.5 exactly (Hann^2, 4x overlap).
__device__ __forceinline__ float ola_at(const float* __restrict__ frames, int c, int t)
{
    int tt = t + PAD;
    int fhi = tt >> 9;
    if (tt >= (N_FFT - HOP) && fhi <= NFRAMES - 1) {
        const float* base = frames + c * NFRAMES * N_FFT;
        int f = fhi - 3;
        int n = tt - f * HOP;   // in [1536, 2048)
        float s = base[f * N_FFT + n]
                + base[(f + 1) * N_FFT + (n - HOP)]
                + base[(f + 2) * N_FFT + (n - 2 * HOP)]
                + base[(f + 3) * N_FFT + (n - 3 * HOP)];
        return s * (2.f / 3.f);
    }
    int fmax = fhi;                                    if (fmax > NFRAMES - 1) fmax = NFRAMES - 1;
    int fmin = (tt - (N_FFT - 1) + (HOP - 1)) / HOP;   if (fmin < 0) fmin = 0;
    float sum = 0.f, ws = 0.f;
    for (int f = fmin; f <= fmax; ++f) {
        int n = tt - f * HOP;
        sum += frames[(c * NFRAMES + f) * N_FFT + n];
        float w = g_win[n];
        ws += w * w;
    }
    return sum / (ws > 1e-11f ? ws : 1.f);
}

__global__ void ola_kernel(const float* __restrict__ frames, float* __restrict__ out)
{
    int idx = blockIdx.x * blockDim.x + threadIdx.x;
    if (idx >= NCH * NT) return;
    int c = idx / NT;
    int t = idx - c * NT;
    out[idx] = ola_at(frames, c, t);
}

// final OLA fused with gain-reduction computation
__global__ void ola_gr_kernel(const float* __restrict__ frames, float* __restrict__ out,
                              float* __restrict__ gr,
                              const float* __restrict__ thr_p, const float* __restrict__ ratio_p)
{
    int idx = blockIdx.x * blockDim.x + threadIdx.x;
    if (idx >= NCH * NT) return;
    int c = idx / NT;
    int t = idx - c * NT;
    float v = ola_at(frames, c, t);
    out[idx] = v;
    float thr = thr_p[0];
    float ratio = ratio_p[0];
    float aa = fabsf(v) + 1e-8f;
    float adb = 20.f * __log10f(aa);
    gr[idx] = fmaxf(adb - thr, 0.f) * (1.f - 1.f / ratio);
}

// Warp-cooperative compressor scan v5.
// CHUNK=256 doubles the grid to 176 blocks (>=148) — targets the documented
// low-grid I$ issue throttle (+28% steady at <148 blocks with large bodies),
// and the single prefetch buffer halves the unrolled body size. Per-warp work
// is otherwise unchanged (wall time = per-warp duration; single wave).
// Recurrence (exact, branchless): state' = max(fma(1-a_att,s,a_att*g), fma(1-a_rel,s,a_rel*g))
__global__ void __launch_bounds__(64, 2)
scan_kernel(const float* __restrict__ gr, float* __restrict__ gs,
            const float* __restrict__ att_p, const float* __restrict__ rel_p)
{
    __shared__ float sbuf[2][2][64][33];   // [warp][dblbuf][row=chunk][col=step]

    const int w = threadIdx.x >> 5;
    const int lane = threadIdx.x & 31;
    const int warpGlobal = blockIdx.x * 2 + w;
    const int chunkBase = warpGlobal * 64;     // max 175*64=11200 < NC
    const int c = blockIdx.y;

    const float a_att = 1.f - __expf(-1.f / (att_p[0] * 48000.f));
    const float a_rel = 1.f - __expf(-1.f / (rel_p[0] * 48000.f));
    const float m_att = 1.f - a_att, m_rel = 1.f - a_rel;

    const float* grc = gr + c * NT;
    float* gsc = gs + c * NT;

    const int row0 = lane >> 3;          // 0..3
    const int quad = (lane & 7) << 2;    // 0,4,..,28
    const bool clampW = (warpGlobal == 0) || (chunkBase + 64 > NC);
    const bool guardW = (warpGlobal == 0);

    float state0 = 0.f, state1 = 0.f;
    float4 nx[16];

#define STEP0(gv) state0 = fmaxf(fmaf(m_att, state0, a_att * (gv)), fmaf(m_rel, state0, a_rel * (gv)))
#define STEP1(gv) state1 = fmaxf(fmaf(m_att, state1, a_att * (gv)), fmaf(m_rel, state1, a_rel * (gv)))

// 16 x LDG.128 per lane: load i covers row i*4+row0, cols quad..quad+3 of tile dd
#define LOADT(dd) do {                                                        \
        int _tb = chunkBase * CHUNK - WARM + (dd) * 32 + quad;                \
        if (clampW) {                                                         \
            _Pragma("unroll")                                                 \
            for (int i = 0; i < 16; ++i) {                                    \
                int _a = _tb + (i * 4 + row0) * CHUNK;                        \
                _a = max(0, min(_a, NT - 4));                                 \
                nx[i] = *(const float4*)(grc + _a);                           \
            }                                                                 \
        } else {                                                              \
            _Pragma("unroll")                                                 \
            for (int i = 0; i < 16; ++i)                                      \
                nx[i] = *(const float4*)(grc + _tb + (i * 4 + row0) * CHUNK); \
        }                                                                     \
    } while (0)

#define STORET(bb) do {                                                       \
        _Pragma("unroll")                                                     \
        for (int i = 0; i < 16; ++i) {                                        \
            int _r = i * 4 + row0;                                            \
            sbuf[w][bb][_r][quad + 0] = nx[i].x;                              \
            sbuf[w][bb][_r][quad + 1] = nx[i].y;                              \
            sbuf[w][bb][_r][quad + 2] = nx[i].z;                              \
            sbuf[w][bb][_r][quad + 3] = nx[i].w;                              \
        }                                                                     \
    } while (0)

    LOADT(0);
    STORET(0);
    __syncwarp();

    // ---- warm phase (no output) ----
    for (int d = 0; d < WARMTILES; ++d) {
        const int b = d & 1;
        LOADT(d + 1);
        const int tf0 = (chunkBase + lane) * CHUNK - WARM + d * 32;
#pragma unroll
        for (int grp = 0; grp < 4; ++grp) {
            float p0[8], p1[8];
#pragma unroll
            for (int j = 0; j < 8; ++j) {
                p0[j] = sbuf[w][b][lane][grp * 8 + j];
                p1[j] = sbuf[w][b][32 + lane][grp * 8 + j];
            }
            if (guardW) {
#pragma unroll
                for (int j = 0; j < 8; ++j) {
                    if (tf0 + grp * 8 + j >= 1) STEP0(p0[j]);
                    STEP1(p1[j]);   // second-half chunks always have full history
                }
            } else {
#pragma unroll
                for (int j = 0; j < 8; ++j) { STEP0(p0[j]); STEP1(p1[j]); }
            }
        }
        STORET((d + 1) & 1);
        __syncwarp();
    }

    // ---- store phase ----
    for (int d = WARMTILES; d < NTILES; ++d) {
        const int b = d & 1;
        if (d + 1 < NTILES) LOADT(d + 1);
        const int tf0 = (chunkBase + lane) * CHUNK - WARM + d * 32;
#pragma unroll
        for (int grp = 0; grp < 4; ++grp) {
            float p0[8], p1[8];
#pragma unroll
            for (int j = 0; j < 8; ++j) {
                p0[j] = sbuf[w][b][lane][grp * 8 + j];
                p1[j] = sbuf[w][b][32 + lane][grp * 8 + j];
            }
            if (guardW) {
#pragma unroll
                for (int j = 0; j < 8; ++j) {
                    if (tf0 + grp * 8 + j >= 1) STEP0(p0[j]);
                    STEP1(p1[j]);
                    sbuf[w][b][lane][grp * 8 + j] = state0;        // t=0 -> state0==0 -> gs[0]=0
                    sbuf[w][b][32 + lane][grp * 8 + j] = state1;
                }
            } else {
#pragma unroll
                for (int j = 0; j < 8; ++j) {
                    STEP0(p0[j]); STEP1(p1[j]);
                    sbuf[w][b][lane][grp * 8 + j] = state0;
                    sbuf[w][b][32 + lane][grp * 8 + j] = state1;
                }
            }
        }
        __syncwarp();
        // cooperative coalesced store of 64 rows
        int toff = (d - WARMTILES) * 32 + lane;
#pragma unroll 8
        for (int r = 0; r < 64; ++r) {
            int ch = chunkBase + r;
            if (ch < NC) gsc[ch * CHUNK + toff] = sbuf[w][b][r][lane];
        }
        if (d + 1 < NTILES) STORET((d + 1) & 1);
        __syncwarp();
    }
#undef STEP0
#undef STEP1
#undef LOADT
#undef STORET
}

// apply smoothed gain + makeup, then saturation
__global__ void final_kernel(const float* __restrict__ x, const float* __restrict__ gs,
                             float* __restrict__ out,
                             const float* __restrict__ makeup_p, const float* __restrict__ sat_p)
{
    int idx = blockIdx.x * blockDim.x + threadIdx.x;
    if (idx >= NCH * NT) return;
    float mk = makeup_p[0];
    float sat = sat_p[0];
    float xv = x[idx];
    float aa = fabsf(xv) + 1e-8f;
    float gl = __expf((mk - gs[idx]) * 0.05f * LN10_F);
    float sgn = (xv > 0.f) ? 1.f : ((xv < 0.f) ? -1.f : 0.f);
    float y = sgn * aa * gl;
    if (sat > 1.f) {
        float z = y * sat;
        float e = __expf(2.f * z);
        y = ((e - 1.f) / (e + 1.f)) / sat;
    }
    out[idx] = y;
}

extern "C" void kernel_launch(void* const* d_in, const int* in_sizes, int n_in,
                              void* d_out, int out_size)
{
    const float* audio      = (const float*)d_in[0];
    const float* eq_low     = (const float*)d_in[1];
    const float* eq_lowmid  = (const float*)d_in[2];
    const float* eq_highmid = (const float*)d_in[3];
    const float* eq_high    = (const float*)d_in[4];
    const float* thr        = (const float*)d_in[5];
    const float* ratio      = (const float*)d_in[6];
    const float* attack     = (const float*)d_in[7];
    const float* release    = (const float*)d_in[8];
    const float* makeup     = (const float*)d_in[9];
    const float* satur      = (const float*)d_in[10];
    float* out = (float*)d_out;

    float *sigA, *sigB, *frames;
    cudaGetSymbolAddress((void**)&sigA, g_sigA);
    cudaGetSymbolAddress((void**)&sigB, g_sigB);
    cudaGetSymbolAddress((void**)&frames, g_frames);
    float* gs = frames;   // frames buffer reused after final OLA

    dim3 gEq(NPAIRS, NCH);
    const int EW = 256;
    int ewBlocks = (NCH * NT + EW - 1) / EW;

    win_init_kernel<<<(N_FFT + 255) / 256, 256>>>();

    // EQ band chain (ping-pong)
    eq_pair_kernel<<<gEq, 128>>>(audio, frames, eq_low, 100.f);
    ola_kernel<<<ewBlocks, EW>>>(frames, sigA);
    eq_pair_kernel<<<gEq, 128>>>(sigA, frames, eq_lowmid, 500.f);
    ola_kernel<<<ewBlocks, EW>>>(frames, sigB);
    eq_pair_kernel<<<gEq, 128>>>(sigB, frames, eq_highmid, 3000.f);
    ola_kernel<<<ewBlocks, EW>>>(frames, sigA);
    eq_pair_kernel<<<gEq, 128>>>(sigA, frames, eq_high, 10000.f);
    // band 4 OLA fused with gain-reduction: audio -> sigB, gr -> sigA
    ola_gr_kernel<<<ewBlocks, EW>>>(frames, sigB, sigA, thr, ratio);

    // dual-chain warp-cooperative compressor envelope (gs into frames buffer)
    // 176 warps per channel (64 chunks each), 2 warps per 64-thread block -> 176 blocks
    dim3 gScan(88, NCH);
    scan_kernel<<<gScan, 64>>>(sigA, gs, attack, release);

    // gain + saturation
    final_kernel<<<ewBlocks, EW>>>(sigB, gs, out, makeup, satur);
}

// round 15
// speedup vs baseline: 1.5764x; 1.1918x over previous
#include <cuda_runtime.h>
#include <math.h>

#define N_FFT   2048
#define HOP     512
#define NT      2880000
#define NFRAMES 5626            // 1 + NT/HOP
#define NPAIRS  2813            // NFRAMES/2
#define PAD     1024            // N_FFT/2
#define NCH     2

#define CHUNK     256
#define WARM      13312
#define NC        11250         // NT / CHUNK (exact)
#define SPAN      512           // samples stored per lane (2 chained chunks)
#define NTILES2   432           // (WARM + SPAN) / 32
#define WARMT2    416           // WARM / 32

#define TWO_PI_F 6.2831853071795864769f
#define LN10_F   2.3025850929940457f

// Scratch (device globals — no allocation allowed)
__device__ float g_sigA[NCH * NT];
__device__ float g_sigB[NCH * NT];
__device__ float g_frames[NCH * NFRAMES * N_FFT];   // reused as gs after OLA4
__device__ float g_win[N_FFT];

struct C2 { float x, y; };
__device__ __forceinline__ C2 cmulC(C2 a, C2 b) { return { a.x*b.x - a.y*b.y, a.x*b.y + a.y*b.x }; }
__device__ __forceinline__ C2 caddC(C2 a, C2 b) { return { a.x + b.x, a.y + b.y }; }
__device__ __forceinline__ C2 csubC(C2 a, C2 b) { return { a.x - b.x, a.y - b.y }; }

__device__ __forceinline__ int SWZ(int p) { return p + (p >> 5); }

// fill hann window (accurate path, computed once per launch)
__global__ void win_init_kernel()
{
    int j = blockIdx.x * blockDim.x + threadIdx.x;
    if (j < N_FFT)
        g_win[j] = 0.5f - 0.5f * cosf((TWO_PI_F / (float)N_FFT) * (float)j);
}

template<int SGN>
__device__ __forceinline__ void dft8(C2 v[8]) {
    const float r = 0.70710678118654752f;
    const float S = (float)SGN;
    C2 a0 = caddC(v[0], v[4]), a1 = csubC(v[0], v[4]);
    C2 a2 = caddC(v[2], v[6]), a3 = csubC(v[2], v[6]);
    C2 E0 = caddC(a0, a2), E2 = csubC(a0, a2);
    C2 E1 = { a1.x - S * a3.y, a1.y + S * a3.x };
    C2 E3 = { a1.x + S * a3.y, a1.y - S * a3.x };
    C2 b0 = caddC(v[1], v[5]), b1 = csubC(v[1], v[5]);
    C2 b2 = caddC(v[3], v[7]), b3 = csubC(v[3], v[7]);
    C2 O0 = caddC(b0, b2), O2 = csubC(b0, b2);
    C2 O1 = { b1.x - S * b3.y, b1.y + S * b3.x };
    C2 O3 = { b1.x + S * b3.y, b1.y - S * b3.x };
    C2 T1 = { r * (O1.x - S * O1.y), r * (O1.y + S * O1.x) };
    C2 T2 = { -S * O2.y, S * O2.x };
    C2 T3 = { -r * (O3.x + S * O3.y), r * (S * O3.x - O3.y) };
    v[0] = caddC(E0, O0); v[4] = csubC(E0, O0);
    v[1] = caddC(E1, T1); v[5] = csubC(E1, T1);
    v[2] = caddC(E2, T2); v[6] = csubC(E2, T2);
    v[3] = caddC(E3, T3); v[7] = csubC(E3, T3);
}

// 16-point DFT: two dft8 halves + constant rotations
template<int SGN>
__device__ __forceinline__ void dft16(C2 v[16]) {
    const float S = (float)SGN;
    const float c1 = 0.92387953251128675613f;   // cos(pi/8)
    const float s1 = 0.38268343236508977173f;   // sin(pi/8)
    const float r  = 0.70710678118654752440f;
    C2 e[8], o[8];
#pragma unroll
    for (int i = 0; i < 8; ++i) { e[i] = v[2*i]; o[i] = v[2*i+1]; }
    dft8<SGN>(e);
    dft8<SGN>(o);
    o[1] = cmulC(o[1], C2{ c1, S*s1});
    o[2] = cmulC(o[2], C2{ r,  S*r });
    o[3] = cmulC(o[3], C2{ s1, S*c1});
    o[4] = C2{ -S*o[4].y, S*o[4].x };
    o[5] = cmulC(o[5], C2{-s1, S*c1});
    o[6] = cmulC(o[6], C2{-r,  S*r });
    o[7] = cmulC(o[7], C2{-c1, S*s1});
#pragma unroll
    for (int k = 0; k < 8; ++k) { v[k] = caddC(e[k], o[k]); v[k+8] = csubC(e[k], o[k]); }
}

// twiddle powers W[1..15] of w1 via a depth-4 product tree
__device__ __forceinline__ void twiddle_pows(C2 w1, C2 W[16]) {
    W[1] = w1;
    W[2] = cmulC(w1, w1);
    W[4] = cmulC(W[2], W[2]);
    W[8] = cmulC(W[4], W[4]);
    W[3] = cmulC(W[2], w1);
    W[5] = cmulC(W[4], w1);
    W[6] = cmulC(W[4], W[2]);
    W[7] = cmulC(W[4], W[3]);
    W[9]  = cmulC(W[8], w1);
    W[10] = cmulC(W[8], W[2]);
    W[11] = cmulC(W[8], W[3]);
    W[12] = cmulC(W[8], W[4]);
    W[13] = cmulC(W[8], W[5]);
    W[14] = cmulC(W[8], W[6]);
    W[15] = cmulC(W[8], W[7]);
}

// one radix-16 exchange stage (smem -> smem)
template<int SGN>
__device__ __forceinline__ void stage16(float2* sh, int M, int j, int base) {
    const int span = M >> 4;
    const int p0 = base + j;
    C2 v[16];
#pragma unroll
    for (int k = 0; k < 16; ++k) {
        float2 t = sh[SWZ(p0 + k * span)];
        v[k] = { t.x, t.y };
    }
    float sn, cs;
    __sincosf(((float)SGN * TWO_PI_F) * ((float)j / (float)M), &sn, &cs);
    C2 W[16];
    twiddle_pows(C2{ cs, sn }, W);
    if (SGN < 0) {
        dft16<-1>(v);
#pragma unroll
        for (int k = 1; k < 16; ++k) v[k] = cmulC(v[k], W[k]);
    } else {
#pragma unroll
        for (int k = 1; k < 16; ++k) v[k] = cmulC(v[k], W[k]);
        dft16<1>(v);
    }
#pragma unroll
    for (int k = 0; k < 16; ++k)
        sh[SWZ(p0 + k * span)] = make_float2(v[k].x, v[k].y);
}

// One block = one (channel, frame-pair). Two real frames packed into one complex FFT.
// 2048 = 16 x 16 x 8; first/last radix-16 stages fused with gmem load/store.
// storage p = d1*128 + d2*8 + i  <->  frequency k = d1 + 16*d2 + 256*i
__global__ void __launch_bounds__(128)
eq_pair_kernel(const float* __restrict__ x, float* __restrict__ frames,
               const float* __restrict__ gain_db_ptr, float fc)
{
    __shared__ float2 sh[N_FFT + (N_FFT >> 5)];

    const int tid = threadIdx.x;
    const int P = blockIdx.x;
    const int c = blockIdx.y;
    const int f0 = 2 * P;

    const float* xc = x + c * NT;

    // ---- fused: windowed reflect-pad load + first forward radix-16 stage
    {
        C2 v[16];
#pragma unroll
        for (int k = 0; k < 16; ++k) {
            int j = tid + 128 * k;
            float w = g_win[j];
            int s0 = f0 * HOP + j - PAD;
            if (s0 < 0) s0 = -s0;
            if (s0 >= NT) s0 = 2 * NT - 2 - s0;
            int s1 = (f0 + 1) * HOP + j - PAD;
            if (s1 < 0) s1 = -s1;
            if (s1 >= NT) s1 = 2 * NT - 2 - s1;
            v[k] = { xc[s0] * w, xc[s1] * w };
        }
        float sn, cs;
        __sincosf(-(TWO_PI_F) * ((float)tid / (float)N_FFT), &sn, &cs);
        C2 W[16];
        twiddle_pows(C2{ cs, sn }, W);
        dft16<-1>(v);
#pragma unroll
        for (int k = 1; k < 16; ++k) v[k] = cmulC(v[k], W[k]);
#pragma unroll
        for (int k = 0; k < 16; ++k)
            sh[SWZ(tid + k * 128)] = make_float2(v[k].x, v[k].y);
    }
    __syncthreads();

    stage16<-1>(sh, 128, tid & 7, (tid >> 3) << 7);
    __syncthreads();

    // fused: forward radix-8 + mask + inverse radix-8 (2 groups/thread)
    {
        float gdb = gain_db_ptr[0];
        float gm1 = __expf(gdb * 0.05f * LN10_F) - 1.f;
        float inv_fc = 1.f / fc;
#pragma unroll
        for (int h = 0; h < 2; ++h) {
            int base = tid * 16 + h * 8;
            C2 u[8];
#pragma unroll
            for (int i = 0; i < 8; ++i) {
                float2 t = sh[SWZ(base + i)];
                u[i] = { t.x, t.y };
            }
            dft8<-1>(u);
            int d1 = (base >> 7) & 15, d2 = (base >> 3) & 15;
            int kbase = d1 + (d2 << 4);
#pragma unroll
            for (int i = 0; i < 8; ++i) {
                int kk = kbase + (i << 8);
                int ks = min(kk, N_FFT - kk);
                float fr = (float)ks * (24000.f / 1024.f);
                float rr = (fr - fc) * inv_fc;    // q = 1
                float fac = 1.f + gm1 * __expf(-rr * rr);
                u[i].x *= fac; u[i].y *= fac;
            }
            dft8<1>(u);
#pragma unroll
            for (int i = 0; i < 8; ++i)
                sh[SWZ(base + i)] = make_float2(u[i].x, u[i].y);
        }
    }
    __syncthreads();

    stage16<1>(sh, 128, tid & 7, (tid >> 3) << 7);
    __syncthreads();

    // ---- fused: last inverse radix-16 stage + windowed store to gmem
    {
        C2 v[16];
#pragma unroll
        for (int k = 0; k < 16; ++k) {
            float2 t = sh[SWZ(tid + k * 128)];
            v[k] = { t.x, t.y };
        }
        float sn, cs;
        __sincosf((TWO_PI_F) * ((float)tid / (float)N_FFT), &sn, &cs);
        C2 W[16];
        twiddle_pows(C2{ cs, sn }, W);
#pragma unroll
        for (int k = 1; k < 16; ++k) v[k] = cmulC(v[k], W[k]);
        dft16<1>(v);
        float* fo0 = frames + (c * NFRAMES + f0) * N_FFT;
        float* fo1 = fo0 + N_FFT;
#pragma unroll
        for (int k = 0; k < 16; ++k) {
            int j = tid + 128 * k;
            float s = g_win[j] * (1.f / (float)N_FFT);
            fo0[j] = v[k].x * s;
            fo1[j] = v[k].y * s;
        }
    }
}

// OLA. Interior (all 4 frames present): wsum == 1.5 exactly (Hann^2, 4x overlap).
__device__ __forceinline__ float ola_at(const float* __restrict__ frames, int c, int t)
{
    int tt = t + PAD;
    int fhi = tt >> 9;
    if (tt >= (N_FFT - HOP) && fhi <= NFRAMES - 1) {
        const float* base = frames + c * NFRAMES * N_FFT;
        int f = fhi - 3;
        int n = tt - f * HOP;   // in [1536, 2048)
        float s = base[f * N_FFT + n]
                + base[(f + 1) * N_FFT + (n - HOP)]
                + base[(f + 2) * N_FFT + (n - 2 * HOP)]
                + base[(f + 3) * N_FFT + (n - 3 * HOP)];
        return s * (2.f / 3.f);
    }
    int fmax = fhi;                                    if (fmax > NFRAMES - 1) fmax = NFRAMES - 1;
    int fmin = (tt - (N_FFT - 1) + (HOP - 1)) / HOP;   if (fmin < 0) fmin = 0;
    float sum = 0.f, ws = 0.f;
    for (int f = fmin; f <= fmax; ++f) {
        int n = tt - f * HOP;
        sum += frames[(c * NFRAMES + f) * N_FFT + n];
        float w = g_win[n];
        ws += w * w;
    }
    return sum / (ws > 1e-11f ? ws : 1.f);
}

__global__ void ola_kernel(const float* __restrict__ frames, float* __restrict__ out)
{
    int idx = blockIdx.x * blockDim.x + threadIdx.x;
    if (idx >= NCH * NT) return;
    int c = idx / NT;
    int t = idx - c * NT;
    out[idx] = ola_at(frames, c, t);
}

// final OLA fused with gain-reduction computation
__global__ void ola_gr_kernel(const float* __restrict__ frames, float* __restrict__ out,
                              float* __restrict__ gr,
                              const float* __restrict__ thr_p, const float* __restrict__ ratio_p)
{
    int idx = blockIdx.x * blockDim.x + threadIdx.x;
    if (idx >= NCH * NT) return;
    int c = idx / NT;
    int t = idx - c * NT;
    float v = ola_at(frames, c, t);
    out[idx] = v;
    float thr = thr_p[0];
    float ratio = ratio_p[0];
    float aa = fabsf(v) + 1e-8f;
    float adb = 20.f * __log10f(aa);
    gr[idx] = fmaxf(adb - thr, 0.f) * (1.f - 1.f / ratio);
}

// Warp-cooperative compressor scan v6 (chained chunks, single chain per lane).
// Lane l owns TWO CONSECUTIVE-IN-TIME chunks (chunkBase+2l, chunkBase+2l+1) chained
// into ONE stream: after chunk 2l the state continues exactly into chunk 2l+1 (zero
// extra warm-up, exact). This halves steps/LDS/STS/LDG per tile vs the dual-chain
// version while keeping NTILES ~equal — attacks the measured per-tile cost directly.
// Lane stream: samples [chunkBase*256 + l*512 - WARM, chunkBase*256 + l*512 + 512).
// Recurrence (exact, branchless): state' = max(fma(1-a_att,s,a_att*g), fma(1-a_rel,s,a_rel*g))
__global__ void __launch_bounds__(64, 2)
scan_kernel(const float* __restrict__ gr, float* __restrict__ gs,
            const float* __restrict__ att_p, const float* __restrict__ rel_p)
{
    __shared__ float sbuf[2][2][32][33];   // [warp][dblbuf][row=lane-stream][col=step]

    const int w = threadIdx.x >> 5;
    const int lane = threadIdx.x & 31;
    const int warpGlobal = blockIdx.x * 2 + w;
    const int chunkBase = warpGlobal * 64;     // 176 warps/ch cover 11264 >= NC
    const int c = blockIdx.y;

    const float a_att = 1.f - __expf(-1.f / (att_p[0] * 48000.f));
    const float a_rel = 1.f - __expf(-1.f / (rel_p[0] * 48000.f));
    const float m_att = 1.f - a_att, m_rel = 1.f - a_rel;

    const float* grc = gr + c * NT;
    float* gsc = gs + c * NT;

    const int row0 = lane >> 3;          // 0..3
    const int quad = (lane & 7) << 2;    // 0,4,..,28
    const int gbase = chunkBase * CHUNK - WARM;          // stream base of row 0
    const bool clampW = (warpGlobal == 0) || (chunkBase + 64 > NC);
    const bool guardW = (warpGlobal == 0);

    float state = 0.f;
    float4 nx[8];

#define STEP(gv) state = fmaxf(fmaf(m_att, state, a_att * (gv)), fmaf(m_rel, state, a_rel * (gv)))

// 8 x LDG.128 per lane: load i covers row row0+4i, cols quad..quad+3 of tile dd
#define LOADT(dd) do {                                                        \
        int _tb = gbase + (dd) * 32 + quad;                                   \
        if (clampW) {                                                         \
            _Pragma("unroll")                                                 \
            for (int i = 0; i < 8; ++i) {                                     \
                int _a = _tb + (row0 + 4 * i) * SPAN;                         \
                _a = max(0, min(_a, NT - 4));                                 \
                nx[i] = *(const float4*)(grc + _a);                           \
            }                                                                 \
        } else {                                                              \
            _Pragma("unroll")                                                 \
            for (int i = 0; i < 8; ++i)                                       \
                nx[i] = *(const float4*)(grc + _tb + (row0 + 4 * i) * SPAN);  \
        }                                                                     \
    } while (0)

#define STORET(bb) do {                                                       \
        _Pragma("unroll")                                                     \
        for (int i = 0; i < 8; ++i) {                                         \
            int _r = row0 + 4 * i;                                            \
            sbuf[w][bb][_r][quad + 0] = nx[i].x;                              \
            sbuf[w][bb][_r][quad + 1] = nx[i].y;                              \
            sbuf[w][bb][_r][quad + 2] = nx[i].z;                              \
            sbuf[w][bb][_r][quad + 3] = nx[i].w;                              \
        }                                                                     \
    } while (0)

    LOADT(0);
    STORET(0);
    __syncwarp();

    // ---- warm phase (no output) ----
    for (int d = 0; d < WARMT2; ++d) {
        const int b = d & 1;
        LOADT(d + 1);
        float p[32];
#pragma unroll
        for (int j = 0; j < 32; ++j) p[j] = sbuf[w][b][lane][j];
        if (guardW) {
            const int tf0 = gbase + lane * SPAN + d * 32;
#pragma unroll
            for (int j = 0; j < 32; ++j) {
                if (tf0 + j >= 1) STEP(p[j]);
            }
        } else {
#pragma unroll
            for (int j = 0; j < 32; ++j) STEP(p[j]);
        }
        STORET((d + 1) & 1);
        __syncwarp();
    }

    // ---- store phase (last 16 tiles = 512 output samples per lane) ----
    for (int d = WARMT2; d < NTILES2; ++d) {
        const int b = d & 1;
        if (d + 1 < NTILES2) LOADT(d + 1);
        float p[32];
#pragma unroll
        for (int j = 0; j < 32; ++j) p[j] = sbuf[w][b][lane][j];
        if (guardW) {
            const int tf0 = gbase + lane * SPAN + d * 32;
#pragma unroll
            for (int j = 0; j < 32; ++j) {
                if (tf0 + j >= 1) STEP(p[j]);
                sbuf[w][b][lane][j] = state;   // at t=0 state==0 -> gs[0]=0
            }
        } else {
#pragma unroll
            for (int j = 0; j < 32; ++j) {
                STEP(p[j]);
                sbuf[w][b][lane][j] = state;
            }
        }
        __syncwarp();
        // cooperative coalesced store: row r col lane -> t = (chunkBase+2r)*256 + s*32 + lane
        const int s = d - WARMT2;
#pragma unroll 8
        for (int r = 0; r < 32; ++r) {
            int tout = (chunkBase + 2 * r) * CHUNK + s * 32 + lane;
            if (tout < NT) gsc[tout] = sbuf[w][b][r][lane];
        }
        if (d + 1 < NTILES2) STORET((d + 1) & 1);
        __syncwarp();
    }
#undef STEP
#undef LOADT
#undef STORET
}

// apply smoothed gain + makeup, then saturation
__global__ void final_kernel(const float* __restrict__ x, const float* __restrict__ gs,
                             float* __restrict__ out,
                             const float* __restrict__ makeup_p, const float* __restrict__ sat_p)
{
    int idx = blockIdx.x * blockDim.x + threadIdx.x;
    if (idx >= NCH * NT) return;
    float mk = makeup_p[0];
    float sat = sat_p[0];
    float xv = x[idx];
    float aa = fabsf(xv) + 1e-8f;
    float gl = __expf((mk - gs[idx]) * 0.05f * LN10_F);
    float sgn = (xv > 0.f) ? 1.f : ((xv < 0.f) ? -1.f : 0.f);
    float y = sgn * aa * gl;
    if (sat > 1.f) {
        float z = y * sat;
        float e = __expf(2.f * z);
        y = ((e - 1.f) / (e + 1.f)) / sat;
    }
    out[idx] = y;
}

extern "C" void kernel_launch(void* const* d_in, const int* in_sizes, int n_in,
                              void* d_out, int out_size)
{
    const float* audio      = (const float*)d_in[0];
    const float* eq_low     = (const float*)d_in[1];
    const float* eq_lowmid  = (const float*)d_in[2];
    const float* eq_highmid = (const float*)d_in[3];
    const float* eq_high    = (const float*)d_in[4];
    const float* thr        = (const float*)d_in[5];
    const float* ratio      = (const float*)d_in[6];
    const float* attack     = (const float*)d_in[7];
    const float* release    = (const float*)d_in[8];
    const float* makeup     = (const float*)d_in[9];
    const float* satur      = (const float*)d_in[10];
    float* out = (float*)d_out;

    float *sigA, *sigB, *frames;
    cudaGetSymbolAddress((void**)&sigA, g_sigA);
    cudaGetSymbolAddress((void**)&sigB, g_sigB);
    cudaGetSymbolAddress((void**)&frames, g_frames);
    float* gs = frames;   // frames buffer reused after final OLA

    dim3 gEq(NPAIRS, NCH);
    const int EW = 256;
    int ewBlocks = (NCH * NT + EW - 1) / EW;

    win_init_kernel<<<(N_FFT + 255) / 256, 256>>>();

    // EQ band chain (ping-pong)
    eq_pair_kernel<<<gEq, 128>>>(audio, frames, eq_low, 100.f);
    ola_kernel<<<ewBlocks, EW>>>(frames, sigA);
    eq_pair_kernel<<<gEq, 128>>>(sigA, frames, eq_lowmid, 500.f);
    ola_kernel<<<ewBlocks, EW>>>(frames, sigB);
    eq_pair_kernel<<<gEq, 128>>>(sigB, frames, eq_highmid, 3000.f);
    ola_kernel<<<ewBlocks, EW>>>(frames, sigA);
    eq_pair_kernel<<<gEq, 128>>>(sigA, frames, eq_high, 10000.f);
    // band 4 OLA fused with gain-reduction: audio -> sigB, gr -> sigA
    ola_gr_kernel<<<ewBlocks, EW>>>(frames, sigB, sigA, thr, ratio);

    // chained-chunk warp-cooperative compressor envelope (gs into frames buffer)
    // 176 warps per channel (64 chunks each, 2 chained per lane), 2 warps/block
    dim3 gScan(88, NCH);
    scan_kernel<<<gScan, 64>>>(sigA, gs, attack, release);

    // gain + saturation
    final_kernel<<<ewBlocks, EW>>>(sigB, gs, out, makeup, satur);
}

// round 16
// speedup vs baseline: 1.6535x; 1.0489x over previous
#include <cuda_runtime.h>
#include <math.h>

#define N_FFT   2048
#define HOP     512
#define NT      2880000
#define NFRAMES 5626            // 1 + NT/HOP
#define NPAIRS  2813            // NFRAMES/2
#define PAD     1024            // N_FFT/2
#define NCH     2

#define CHUNK     256
#define WARM      13312
#define NC        11250         // NT / CHUNK (exact)
#define SPAN      512           // samples stored per lane (2 chained chunks)
#define NTILES2   432           // (WARM + SPAN) / 32
#define WARMT2    416           // WARM / 32

#define TWO_PI_F 6.2831853071795864769f
#define LN10_F   2.3025850929940457f

// Scratch (device globals — no allocation allowed)
__device__ float g_sigA[NCH * NT];
__device__ float g_sigB[NCH * NT];
__device__ float g_frames[NCH * NFRAMES * N_FFT];   // reused as gs after OLA4
__device__ float g_win[N_FFT];

struct C2 { float x, y; };
__device__ __forceinline__ C2 cmulC(C2 a, C2 b) { return { a.x*b.x - a.y*b.y, a.x*b.y + a.y*b.x }; }
__device__ __forceinline__ C2 caddC(C2 a, C2 b) { return { a.x + b.x, a.y + b.y }; }
__device__ __forceinline__ C2 csubC(C2 a, C2 b) { return { a.x - b.x, a.y - b.y }; }

__device__ __forceinline__ int SWZ(int p) { return p + (p >> 5); }

// fill hann window (accurate path, computed once per launch)
__global__ void win_init_kernel()
{
    int j = blockIdx.x * blockDim.x + threadIdx.x;
    if (j < N_FFT)
        g_win[j] = 0.5f - 0.5f * cosf((TWO_PI_F / (float)N_FFT) * (float)j);
}

template<int SGN>
__device__ __forceinline__ void dft8(C2 v[8]) {
    const float r = 0.70710678118654752f;
    const float S = (float)SGN;
    C2 a0 = caddC(v[0], v[4]), a1 = csubC(v[0], v[4]);
    C2 a2 = caddC(v[2], v[6]), a3 = csubC(v[2], v[6]);
    C2 E0 = caddC(a0, a2), E2 = csubC(a0, a2);
    C2 E1 = { a1.x - S * a3.y, a1.y + S * a3.x };
    C2 E3 = { a1.x + S * a3.y, a1.y - S * a3.x };
    C2 b0 = caddC(v[1], v[5]), b1 = csubC(v[1], v[5]);
    C2 b2 = caddC(v[3], v[7]), b3 = csubC(v[3], v[7]);
    C2 O0 = caddC(b0, b2), O2 = csubC(b0, b2);
    C2 O1 = { b1.x - S * b3.y, b1.y + S * b3.x };
    C2 O3 = { b1.x + S * b3.y, b1.y - S * b3.x };
    C2 T1 = { r * (O1.x - S * O1.y), r * (O1.y + S * O1.x) };
    C2 T2 = { -S * O2.y, S * O2.x };
    C2 T3 = { -r * (O3.x + S * O3.y), r * (S * O3.x - O3.y) };
    v[0] = caddC(E0, O0); v[4] = csubC(E0, O0);
    v[1] = caddC(E1, T1); v[5] = csubC(E1, T1);
    v[2] = caddC(E2, T2); v[6] = csubC(E2, T2);
    v[3] = caddC(E3, T3); v[7] = csubC(E3, T3);
}

// 16-point DFT: two dft8 halves + constant rotations
template<int SGN>
__device__ __forceinline__ void dft16(C2 v[16]) {
    const float S = (float)SGN;
    const float c1 = 0.92387953251128675613f;   // cos(pi/8)
    const float s1 = 0.38268343236508977173f;   // sin(pi/8)
    const float r  = 0.70710678118654752440f;
    C2 e[8], o[8];
#pragma unroll
    for (int i = 0; i < 8; ++i) { e[i] = v[2*i]; o[i] = v[2*i+1]; }
    dft8<SGN>(e);
    dft8<SGN>(o);
    o[1] = cmulC(o[1], C2{ c1, S*s1});
    o[2] = cmulC(o[2], C2{ r,  S*r });
    o[3] = cmulC(o[3], C2{ s1, S*c1});
    o[4] = C2{ -S*o[4].y, S*o[4].x };
    o[5] = cmulC(o[5], C2{-s1, S*c1});
    o[6] = cmulC(o[6], C2{-r,  S*r });
    o[7] = cmulC(o[7], C2{-c1, S*s1});
#pragma unroll
    for (int k = 0; k < 8; ++k) { v[k] = caddC(e[k], o[k]); v[k+8] = csubC(e[k], o[k]); }
}

// twiddle powers W[1..15] of w1 via a depth-4 product tree
__device__ __forceinline__ void twiddle_pows(C2 w1, C2 W[16]) {
    W[1] = w1;
    W[2] = cmulC(w1, w1);
    W[4] = cmulC(W[2], W[2]);
    W[8] = cmulC(W[4], W[4]);
    W[3] = cmulC(W[2], w1);
    W[5] = cmulC(W[4], w1);
    W[6] = cmulC(W[4], W[2]);
    W[7] = cmulC(W[4], W[3]);
    W[9]  = cmulC(W[8], w1);
    W[10] = cmulC(W[8], W[2]);
    W[11] = cmulC(W[8], W[3]);
    W[12] = cmulC(W[8], W[4]);
    W[13] = cmulC(W[8], W[5]);
    W[14] = cmulC(W[8], W[6]);
    W[15] = cmulC(W[8], W[7]);
}

// one radix-16 exchange stage (smem -> smem)
template<int SGN>
__device__ __forceinline__ void stage16(float2* sh, int M, int j, int base) {
    const int span = M >> 4;
    const int p0 = base + j;
    C2 v[16];
#pragma unroll
    for (int k = 0; k < 16; ++k) {
        float2 t = sh[SWZ(p0 + k * span)];
        v[k] = { t.x, t.y };
    }
    float sn, cs;
    __sincosf(((float)SGN * TWO_PI_F) * ((float)j / (float)M), &sn, &cs);
    C2 W[16];
    twiddle_pows(C2{ cs, sn }, W);
    if (SGN < 0) {
        dft16<-1>(v);
#pragma unroll
        for (int k = 1; k < 16; ++k) v[k] = cmulC(v[k], W[k]);
    } else {
#pragma unroll
        for (int k = 1; k < 16; ++k) v[k] = cmulC(v[k], W[k]);
        dft16<1>(v);
    }
#pragma unroll
    for (int k = 0; k < 16; ++k)
        sh[SWZ(p0 + k * span)] = make_float2(v[k].x, v[k].y);
}

// One block = one (channel, frame-pair). Two real frames packed into one complex FFT.
// 2048 = 16 x 16 x 8; first/last radix-16 stages fused with gmem load/store.
// storage p = d1*128 + d2*8 + i  <->  frequency k = d1 + 16*d2 + 256*i
__global__ void __launch_bounds__(128)
eq_pair_kernel(const float* __restrict__ x, float* __restrict__ frames,
               const float* __restrict__ gain_db_ptr, float fc)
{
    __shared__ float2 sh[N_FFT + (N_FFT >> 5)];

    const int tid = threadIdx.x;
    const int P = blockIdx.x;
    const int c = blockIdx.y;
    const int f0 = 2 * P;

    const float* xc = x + c * NT;

    // ---- fused: windowed reflect-pad load + first forward radix-16 stage
    {
        C2 v[16];
#pragma unroll
        for (int k = 0; k < 16; ++k) {
            int j = tid + 128 * k;
            float w = g_win[j];
            int s0 = f0 * HOP + j - PAD;
            if (s0 < 0) s0 = -s0;
            if (s0 >= NT) s0 = 2 * NT - 2 - s0;
            int s1 = (f0 + 1) * HOP + j - PAD;
            if (s1 < 0) s1 = -s1;
            if (s1 >= NT) s1 = 2 * NT - 2 - s1;
            v[k] = { xc[s0] * w, xc[s1] * w };
        }
        float sn, cs;
        __sincosf(-(TWO_PI_F) * ((float)tid / (float)N_FFT), &sn, &cs);
        C2 W[16];
        twiddle_pows(C2{ cs, sn }, W);
        dft16<-1>(v);
#pragma unroll
        for (int k = 1; k < 16; ++k) v[k] = cmulC(v[k], W[k]);
#pragma unroll
        for (int k = 0; k < 16; ++k)
            sh[SWZ(tid + k * 128)] = make_float2(v[k].x, v[k].y);
    }
    __syncthreads();

    stage16<-1>(sh, 128, tid & 7, (tid >> 3) << 7);
    __syncthreads();

    // fused: forward radix-8 + mask + inverse radix-8 (2 groups/thread)
    {
        float gdb = gain_db_ptr[0];
        float gm1 = __expf(gdb * 0.05f * LN10_F) - 1.f;
        float inv_fc = 1.f / fc;
#pragma unroll
        for (int h = 0; h < 2; ++h) {
            int base = tid * 16 + h * 8;
            C2 u[8];
#pragma unroll
            for (int i = 0; i < 8; ++i) {
                float2 t = sh[SWZ(base + i)];
                u[i] = { t.x, t.y };
            }
            dft8<-1>(u);
            int d1 = (base >> 7) & 15, d2 = (base >> 3) & 15;
            int kbase = d1 + (d2 << 4);
#pragma unroll
            for (int i = 0; i < 8; ++i) {
                int kk = kbase + (i << 8);
                int ks = min(kk, N_FFT - kk);
                float fr = (float)ks * (24000.f / 1024.f);
                float rr = (fr - fc) * inv_fc;    // q = 1
                float fac = 1.f + gm1 * __expf(-rr * rr);
                u[i].x *= fac; u[i].y *= fac;
            }
            dft8<1>(u);
#pragma unroll
            for (int i = 0; i < 8; ++i)
                sh[SWZ(base + i)] = make_float2(u[i].x, u[i].y);
        }
    }
    __syncthreads();

    stage16<1>(sh, 128, tid & 7, (tid >> 3) << 7);
    __syncthreads();

    // ---- fused: last inverse radix-16 stage + windowed store to gmem
    {
        C2 v[16];
#pragma unroll
        for (int k = 0; k < 16; ++k) {
            float2 t = sh[SWZ(tid + k * 128)];
            v[k] = { t.x, t.y };
        }
        float sn, cs;
        __sincosf((TWO_PI_F) * ((float)tid / (float)N_FFT), &sn, &cs);
        C2 W[16];
        twiddle_pows(C2{ cs, sn }, W);
#pragma unroll
        for (int k = 1; k < 16; ++k) v[k] = cmulC(v[k], W[k]);
        dft16<1>(v);
        float* fo0 = frames + (c * NFRAMES + f0) * N_FFT;
        float* fo1 = fo0 + N_FFT;
#pragma unroll
        for (int k = 0; k < 16; ++k) {
            int j = tid + 128 * k;
            float s = g_win[j] * (1.f / (float)N_FFT);
            fo0[j] = v[k].x * s;
            fo1[j] = v[k].y * s;
        }
    }
}

// OLA. Interior (all 4 frames present): wsum == 1.5 exactly (Hann^2, 4x overlap).
__device__ __forceinline__ float ola_at(const float* __restrict__ frames, int c, int t)
{
    int tt = t + PAD;
    int fhi = tt >> 9;
    if (tt >= (N_FFT - HOP) && fhi <= NFRAMES - 1) {
        const float* base = frames + c * NFRAMES * N_FFT;
        int f = fhi - 3;
        int n = tt - f * HOP;   // in [1536, 2048)
        float s = base[f * N_FFT + n]
                + base[(f + 1) * N_FFT + (n - HOP)]
                + base[(f + 2) * N_FFT + (n - 2 * HOP)]
                + base[(f + 3) * N_FFT + (n - 3 * HOP)];
        return s * (2.f / 3.f);
    }
    int fmax = fhi;                                    if (fmax > NFRAMES - 1) fmax = NFRAMES - 1;
    int fmin = (tt - (N_FFT - 1) + (HOP - 1)) / HOP;   if (fmin < 0) fmin = 0;
    float sum = 0.f, ws = 0.f;
    for (int f = fmin; f <= fmax; ++f) {
        int n = tt - f * HOP;
        sum += frames[(c * NFRAMES + f) * N_FFT + n];
        float w = g_win[n];
        ws += w * w;
    }
    return sum / (ws > 1e-11f ? ws : 1.f);
}

__global__ void ola_kernel(const float* __restrict__ frames, float* __restrict__ out)
{
    int idx = blockIdx.x * blockDim.x + threadIdx.x;
    if (idx >= NCH * NT) return;
    int c = idx / NT;
    int t = idx - c * NT;
    out[idx] = ola_at(frames, c, t);
}

// final OLA fused with gain-reduction computation
__global__ void ola_gr_kernel(const float* __restrict__ frames, float* __restrict__ out,
                              float* __restrict__ gr,
                              const float* __restrict__ thr_p, const float* __restrict__ ratio_p)
{
    int idx = blockIdx.x * blockDim.x + threadIdx.x;
    if (idx >= NCH * NT) return;
    int c = idx / NT;
    int t = idx - c * NT;
    float v = ola_at(frames, c, t);
    out[idx] = v;
    float thr = thr_p[0];
    float ratio = ratio_p[0];
    float aa = fabsf(v) + 1e-8f;
    float adb = 20.f * __log10f(aa);
    gr[idx] = fmaxf(adb - thr, 0.f) * (1.f - 1.f / ratio);
}

// Warp-cooperative compressor scan v7 (chained chunks + software-pipelined tile body).
// Same stream layout as v6 (lane owns 2 consecutive-in-time chunks). New: the tile's
// independent work (rolling LDS preload, one STS per step staging the NEXT tile's
// data from registers loaded a full tile earlier) is interleaved INTO the recurrence
// chain so it issues inside the chain's ~10-cyc RAW windows, instead of as serial
// batch prefixes/suffixes (measured 18 cyc/step vs the ~10 floor).
// Recurrence (exact, branchless): state' = max(fma(1-a_att,s,a_att*g), fma(1-a_rel,s,a_rel*g))
__global__ void __launch_bounds__(64, 2)
scan_kernel(const float* __restrict__ gr, float* __restrict__ gs,
            const float* __restrict__ att_p, const float* __restrict__ rel_p)
{
    __shared__ float sbuf[2][2][32][33];   // [warp][dblbuf][row=lane-stream][col=step]

    const int w = threadIdx.x >> 5;
    const int lane = threadIdx.x & 31;
    const int warpGlobal = blockIdx.x * 2 + w;
    const int chunkBase = warpGlobal * 64;     // 176 warps/ch cover 11264 >= NC
    const int c = blockIdx.y;

    const float a_att = 1.f - __expf(-1.f / (att_p[0] * 48000.f));
    const float a_rel = 1.f - __expf(-1.f / (rel_p[0] * 48000.f));
    const float m_att = 1.f - a_att, m_rel = 1.f - a_rel;

    const float* grc = gr + c * NT;
    float* gsc = gs + c * NT;

    const int row0 = lane >> 3;          // 0..3
    const int quad = (lane & 7) << 2;    // 0,4,..,28
    const int gbase = chunkBase * CHUNK - WARM;          // stream base of row 0
    const bool clampW = (warpGlobal == 0) || (chunkBase + 64 > NC);

    float state = 0.f;
    float4 nxA[8], nxB[8];

#define STEP(gv) state = fmaxf(fmaf(m_att, state, a_att * (gv)), fmaf(m_rel, state, a_rel * (gv)))

// 8 x LDG.128 per lane: load i covers row row0+4i, cols quad..quad+3 of tile dd -> nx
#define LOADT(dd, nx) do {                                                    \
        int _tb = gbase + (dd) * 32 + quad;                                   \
        if (clampW) {                                                         \
            _Pragma("unroll")                                                 \
            for (int i = 0; i < 8; ++i) {                                     \
                int _a = _tb + (row0 + 4 * i) * SPAN;                         \
                _a = max(0, min(_a, NT - 4));                                 \
                nx[i] = *(const float4*)(grc + _a);                           \
            }                                                                 \
        } else {                                                              \
            _Pragma("unroll")                                                 \
            for (int i = 0; i < 8; ++i)                                       \
                nx[i] = *(const float4*)(grc + _tb + (row0 + 4 * i) * SPAN);  \
        }                                                                     \
    } while (0)

// batch store (prologue only)
#define STORET(bb, nx) do {                                                   \
        _Pragma("unroll")                                                     \
        for (int i = 0; i < 8; ++i) {                                         \
            int _r = row0 + 4 * i;                                            \
            sbuf[w][bb][_r][quad + 0] = nx[i].x;                              \
            sbuf[w][bb][_r][quad + 1] = nx[i].y;                              \
            sbuf[w][bb][_r][quad + 2] = nx[i].z;                              \
            sbuf[w][bb][_r][quad + 3] = nx[i].w;                              \
        }                                                                     \
    } while (0)

// pipelined tile body: rolling LDS preload + 1 STS/step staging nx into buffer bb,
// all interleaved into the chain. DOSTS/DOOUT compile-time.
#define TILE_BODY(b, bb, nx, DOSTS, DOOUT) do {                               \
        float p[32];                                                          \
        _Pragma("unroll")                                                     \
        for (int j0 = 0; j0 < 8; ++j0) p[j0] = sbuf[w][b][lane][j0];          \
        const int tf0 = gbase + lane * SPAN + d * 32;                         \
        _Pragma("unroll")                                                     \
        for (int j = 0; j < 32; ++j) {                                        \
            if (j < 24) p[j + 8] = sbuf[w][b][lane][j + 8];                   \
            if (DOSTS) {                                                      \
                const int _i = j >> 2, _cpt = j & 3;                          \
                float _v = (_cpt == 0) ? nx[_i].x : (_cpt == 1) ? nx[_i].y    \
                           : (_cpt == 2) ? nx[_i].z : nx[_i].w;               \
                sbuf[w][bb][row0 + 4 * _i][quad + _cpt] = _v;                 \
            }                                                                 \
            if (tf0 + j >= 1) STEP(p[j]);                                     \
            if (DOOUT) sbuf[w][b][lane][j] = state;                           \
        }                                                                     \
    } while (0)

    // prologue: tile0 staged in buf0; tile1 in flight in nxB
    LOADT(0, nxA);
    STORET(0, nxA);
    LOADT(1, nxB);
    __syncwarp();

    // ---- warm phase (no output) ----
    for (int d = 0; d < WARMT2; ++d) {
        const int b = d & 1, bb = (d + 1) & 1;
        if ((d & 1) == 0) {
            if (d + 2 < NTILES2) LOADT(d + 2, nxA);
            TILE_BODY(b, bb, nxB, true, false);   // stage tile d+1 (in nxB) into bb
        } else {
            if (d + 2 < NTILES2) LOADT(d + 2, nxB);
            TILE_BODY(b, bb, nxA, true, false);
        }
        __syncwarp();
    }

    // ---- store phase (last 16 tiles = 512 output samples per lane) ----
    for (int d = WARMT2; d < NTILES2; ++d) {
        const int b = d & 1, bb = (d + 1) & 1;
        const bool hasNext = (d + 1 < NTILES2);
        if ((d & 1) == 0) {
            if (d + 2 < NTILES2) LOADT(d + 2, nxA);
            if (hasNext) TILE_BODY(b, bb, nxB, true, true);
            else         TILE_BODY(b, bb, nxB, false, true);
        } else {
            if (d + 2 < NTILES2) LOADT(d + 2, nxB);
            if (hasNext) TILE_BODY(b, bb, nxA, true, true);
            else         TILE_BODY(b, bb, nxA, false, true);
        }
        __syncwarp();
        // cooperative coalesced store: row r col lane -> t = (chunkBase+2r)*256 + s*32 + lane
        const int s = d - WARMT2;
#pragma unroll 8
        for (int r = 0; r < 32; ++r) {
            int tout = (chunkBase + 2 * r) * CHUNK + s * 32 + lane;
            if (tout < NT) gsc[tout] = sbuf[w][b][r][lane];
        }
        __syncwarp();
    }
#undef STEP
#undef LOADT
#undef STORET
#undef TILE_BODY
}

// apply smoothed gain + makeup, then saturation
__global__ void final_kernel(const float* __restrict__ x, const float* __restrict__ gs,
                             float* __restrict__ out,
                             const float* __restrict__ makeup_p, const float* __restrict__ sat_p)
{
    int idx = blockIdx.x * blockDim.x + threadIdx.x;
    if (idx >= NCH * NT) return;
    float mk = makeup_p[0];
    float sat = sat_p[0];
    float xv = x[idx];
    float aa = fabsf(xv) + 1e-8f;
    float gl = __expf((mk - gs[idx]) * 0.05f * LN10_F);
    float sgn = (xv > 0.f) ? 1.f : ((xv < 0.f) ? -1.f : 0.f);
    float y = sgn * aa * gl;
    if (sat > 1.f) {
        float z = y * sat;
        float e = __expf(2.f * z);
        y = ((e - 1.f) / (e + 1.f)) / sat;
    }
    out[idx] = y;
}

extern "C" void kernel_launch(void* const* d_in, const int* in_sizes, int n_in,
                              void* d_out, int out_size)
{
    const float* audio      = (const float*)d_in[0];
    const float* eq_low     = (const float*)d_in[1];
    const float* eq_lowmid  = (const float*)d_in[2];
    const float* eq_highmid = (const float*)d_in[3];
    const float* eq_high    = (const float*)d_in[4];
    const float* thr        = (const float*)d_in[5];
    const float* ratio      = (const float*)d_in[6];
    const float* attack     = (const float*)d_in[7];
    const float* release    = (const float*)d_in[8];
    const float* makeup     = (const float*)d_in[9];
    const float* satur      = (const float*)d_in[10];
    float* out = (float*)d_out;

    float *sigA, *sigB, *frames;
    cudaGetSymbolAddress((void**)&sigA, g_sigA);
    cudaGetSymbolAddress((void**)&sigB, g_sigB);
    cudaGetSymbolAddress((void**)&frames, g_frames);
    float* gs = frames;   // frames buffer reused after final OLA

    dim3 gEq(NPAIRS, NCH);
    const int EW = 256;
    int ewBlocks = (NCH * NT + EW - 1) / EW;

    win_init_kernel<<<(N_FFT + 255) / 256, 256>>>();

    // EQ band chain (ping-pong)
    eq_pair_kernel<<<gEq, 128>>>(audio, frames, eq_low, 100.f);
    ola_kernel<<<ewBlocks, EW>>>(frames, sigA);
    eq_pair_kernel<<<gEq, 128>>>(sigA, frames, eq_lowmid, 500.f);
    ola_kernel<<<ewBlocks, EW>>>(frames, sigB);
    eq_pair_kernel<<<gEq, 128>>>(sigB, frames, eq_highmid, 3000.f);
    ola_kernel<<<ewBlocks, EW>>>(frames, sigA);
    eq_pair_kernel<<<gEq, 128>>>(sigA, frames, eq_high, 10000.f);
    // band 4 OLA fused with gain-reduction: audio -> sigB, gr -> sigA
    ola_gr_kernel<<<ewBlocks, EW>>>(frames, sigB, sigA, thr, ratio);

    // pipelined chained-chunk compressor envelope (gs into frames buffer)
    dim3 gScan(88, NCH);
    scan_kernel<<<gScan, 64>>>(sigA, gs, attack, release);

    // gain + saturation
    final_kernel<<<ewBlocks, EW>>>(sigB, gs, out, makeup, satur);
}